// round 12
// baseline (speedup 1.0000x reference)
#include <cuda_runtime.h>
#include <cuda_fp16.h>
#include <math.h>
#include <stdint.h>

#define BDIM 512
#define SLEN 2048
#define BATCH 32
#define NROWS (BATCH*SLEN)
#define KS 19
#define NC 32                    // NCLS * H
#define LOGS 7.6246189861594f    // log(2048)

// ---------------- scratch (static device globals; no allocs) ----------------
__device__ float  g_WqT[NC*BDIM];                  // Wg = ln_g ⊙ WqEff, [c][d]
__device__ float  g_Gs[NC];                        // sum_d Wg[c][d]
__device__ float  g_Bs[NC];                        // sum_d ln_b[d]*W[c][d]
__device__ __half g_Wp1h[BDIM*BDIM];               // Wp1 transposed [n][k], fp16
__device__ __half g_posh[(size_t)NROWS*BDIM];      // conv output, fp16
__device__ float  g_x2[(size_t)NROWS*BDIM];        // x + pos@Wp1 + bp1
__device__ float  g_Ppart[(size_t)BATCH*64*NC*BDIM]; // pooling partials [b][chunk][c][d]
__device__ float  g_A[BATCH*NC];                   // sum attn
__device__ float  g_Mw[BATCH*NC];                  // sum attn*rstd*mean
__device__ float  g_pooled[BATCH*NC*BDIM];         // pooled xn [b][c][d]

// ---------------- helpers ----------------
__device__ __forceinline__ uint32_t s2u(const void* p) {
    uint32_t a;
    asm("{ .reg .u64 t; cvta.to.shared.u64 t, %1; cvt.u32.u64 %0, t; }" : "=r"(a) : "l"(p));
    return a;
}

// ---------------- conv (wavelet coefs fused, smem-tiled) ----------------
#define CTS 64
#define CDC 128
#define SM_CONV ((CTS+18)*CDC*4 + KS*CDC*4)     // 51712
__global__ __launch_bounds__(512) void k_conv(const float* __restrict__ x,
                                              const float* __restrict__ w1,
                                              const float* __restrict__ w2,
                                              const float* __restrict__ w3) {
    extern __shared__ char smc[];
    float (*tile)[CDC]  = (float(*)[CDC])smc;
    float (*scoef)[CDC] = (float(*)[CDC])(smc + (CTS+18)*CDC*4);
    int b  = blockIdx.z;
    int s0 = blockIdx.y * CTS;
    int d0 = blockIdx.x * CDC;
    int tid = threadIdx.x;

    const float C = 0.8673250705840776f;
    const float* ws[3] = {w1, w2, w3};
    for (int i = tid; i < KS*CDC; i += 512) {
        int t = i >> 7, d = i & (CDC-1);
        int dg = d0 + d;
        float xs = (float)(t - 9);
        float sum = 0.f;
        #pragma unroll
        for (int wv = 0; wv < 3; wv++) {
            float scale = ws[wv][dg];
            float shift = ws[wv][BDIM + dg];
            float u = (xs - shift) / scale;
            sum += C * (1.f - u*u) * expf(-0.5f*u*u) * rsqrtf(fabsf(scale));
        }
        scoef[t][d] = sum;
    }

    const int NV = (CTS + 18) * (CDC / 4);
    for (int i = tid; i < NV; i += 512) {
        int r = i / (CDC/4), c4 = i % (CDC/4);
        int s = s0 - 9 + r;
        float4 v = make_float4(0.f, 0.f, 0.f, 0.f);
        if (s >= 0 && s < SLEN)
            v = *(const float4*)&x[((size_t)b*SLEN + s)*BDIM + d0 + c4*4];
        *(float4*)&tile[r][c4*4] = v;
    }
    __syncthreads();

    int dL = tid & (CDC - 1);
    int g  = tid >> 7;
    float coef[KS];
    #pragma unroll
    for (int t = 0; t < KS; t++) coef[t] = scoef[t][dL];

    float acc[16];
    #pragma unroll
    for (int i = 0; i < 16; i++) acc[i] = 0.f;

    #pragma unroll
    for (int j = 0; j < 34; j++) {
        float v = tile[g*16 + j][dL];
        #pragma unroll
        for (int t = 0; t < KS; t++) {
            int s = j - t;
            if (s >= 0 && s < 16) acc[s] += v * coef[t];
        }
    }
    size_t base = ((size_t)b*SLEN + s0 + g*16)*BDIM + d0 + dL;
    #pragma unroll
    for (int i = 0; i < 16; i++)
        g_posh[base + (size_t)i*BDIM] = __float2half(acc[i]);
}

// ------- prep: Wg/Gs/Bs (blocks 0..31); Wp1 fp16 transpose (32..47) -------
__global__ __launch_bounds__(512) void k_prep(const float* __restrict__ cls,
                                              const float* __restrict__ Wq,
                                              const float* __restrict__ Wkv,
                                              const float* __restrict__ Wp1,
                                              const float* __restrict__ ln_g,
                                              const float* __restrict__ ln_b) {
    if (blockIdx.x < 32) {
        __shared__ float q[2][BDIM];
        __shared__ float red2[BDIM];
        int j = threadIdx.x;
        #pragma unroll
        for (int n = 0; n < 2; n++) {
            float acc = 0.f;
            #pragma unroll 16
            for (int d = 0; d < BDIM; d++)
                acc += __ldg(&cls[n*BDIM + d]) * Wq[(size_t)d*BDIM + j];
            q[n][j] = acc;
        }
        __syncthreads();
        int c = blockIdx.x, d = threadIdx.x;
        int n = c >> 4, h = c & 15;
        float acc = 0.f;
        #pragma unroll
        for (int hd = 0; hd < 32; hd++)
            acc += Wkv[(size_t)d*1024 + h*32 + hd] * q[n][h*32 + hd];
        acc *= 0.17677669529663689f;
        float wg = acc * ln_g[d];
        g_WqT[c*BDIM + d] = wg;
        red2[d] = wg;
        __syncthreads();
        for (int off = 256; off; off >>= 1) {
            if (d < off) red2[d] += red2[d + off];
            __syncthreads();
        }
        if (d == 0) g_Gs[c] = red2[0];
        __syncthreads();
        red2[d] = acc * ln_b[d];
        __syncthreads();
        for (int off = 256; off; off >>= 1) {
            if (d < off) red2[d] += red2[d + off];
            __syncthreads();
        }
        if (d == 0) g_Bs[c] = red2[0];
        if (d < BATCH) { g_A[d*NC + c] = 0.f; g_Mw[d*NC + c] = 0.f; }
    } else {
        int nb = (blockIdx.x - 32) * 32;
        int k = threadIdx.x;
        #pragma unroll
        for (int i = 0; i < 32; i++)
            g_Wp1h[(size_t)(nb + i)*BDIM + k] = __float2half(Wp1[(size_t)k*BDIM + nb + i]);
    }
}

// -------- x2 = x + pos @ Wp1 + bp1 (fp16 mma.sync + ldmatrix, 2-stage cp.async) --------
#define GM 128
#define GN 256
#define KCH 64
#define NCHUNK 8
#define AST 72
#define STG_H ((GM + GN) * AST)
#define SM_GEMM (2*STG_H*2)

__global__ __launch_bounds__(256) void k_gemm(const float* __restrict__ x,
                                              const float* __restrict__ bp1) {
    extern __shared__ __half smh[];
    uint32_t sb = s2u(smh);
    int tid  = threadIdx.x;
    int m0   = blockIdx.y * GM;
    int n0   = blockIdx.x * GN;
    int warp = tid >> 5, lane = tid & 31;
    int wm   = (warp & 1) * 64;
    int wn   = (warp >> 1) * 64;
    int gid  = lane >> 2, tig = lane & 3;

    float acc[4][8][4];
    #pragma unroll
    for (int i = 0; i < 4; i++)
        #pragma unroll
        for (int j = 0; j < 8; j++)
            #pragma unroll
            for (int r = 0; r < 4; r++) acc[i][j][r] = 0.f;

    auto load_chunk = [&](int ch, int st) {
        uint32_t ab = sb + (uint32_t)(st * STG_H) * 2u;
        uint32_t bb = ab + GM*AST*2u;
        const __half* As = g_posh + (size_t)m0 * BDIM + ch * KCH;
        #pragma unroll
        for (int it = 0; it < 4; it++) {
            int idx = tid + it * 256;
            int r = idx >> 3, c = idx & 7;
            uint32_t dst = ab + (uint32_t)(r*144 + c*16);
            const __half* src = As + (size_t)r * BDIM + c * 8;
            asm volatile("cp.async.cg.shared.global [%0], [%1], 16;" :: "r"(dst), "l"(src));
        }
        const __half* Bs = g_Wp1h + (size_t)n0 * BDIM + ch * KCH;
        #pragma unroll
        for (int it = 0; it < 8; it++) {
            int idx = tid + it * 256;
            int r = idx >> 3, c = idx & 7;
            uint32_t dst = bb + (uint32_t)(r*144 + c*16);
            const __half* src = Bs + (size_t)r * BDIM + c * 8;
            asm volatile("cp.async.cg.shared.global [%0], [%1], 16;" :: "r"(dst), "l"(src));
        }
        asm volatile("cp.async.commit_group;" ::: "memory");
    };

    load_chunk(0, 0);
    load_chunk(1, 1);

    for (int i = 0; i < NCHUNK; i++) {
        int st = i & 1;
        if (i >= NCHUNK - 1) asm volatile("cp.async.wait_group 0;" ::: "memory");
        else                 asm volatile("cp.async.wait_group 1;" ::: "memory");
        __syncthreads();

        uint32_t abase = sb + (uint32_t)(st * STG_H) * 2u;
        uint32_t bbase = abase + GM*AST*2u;
        int arow_off = (lane & 7) + ((lane >> 3) & 1) * 8;
        int acol_off = (lane >> 4) * 8;
        int brow_off = (lane & 7);
        int bcol_off = ((lane >> 3) & 1) * 8;

        #pragma unroll
        for (int ks = 0; ks < 4; ks++) {
            uint32_t a[4][4], bf[8][2];
            #pragma unroll
            for (int mt = 0; mt < 4; mt++) {
                int m = wm + mt*16 + arow_off;
                uint32_t addr = abase + (uint32_t)(m*144 + (ks*16 + acol_off)*2);
                asm volatile("ldmatrix.sync.aligned.m8n8.x4.shared.b16 {%0,%1,%2,%3}, [%4];"
                             : "=r"(a[mt][0]), "=r"(a[mt][1]), "=r"(a[mt][2]), "=r"(a[mt][3])
                             : "r"(addr));
            }
            #pragma unroll
            for (int nt = 0; nt < 8; nt++) {
                int n = wn + nt*8 + brow_off;
                uint32_t addr = bbase + (uint32_t)(n*144 + (ks*16 + bcol_off)*2);
                asm volatile("ldmatrix.sync.aligned.m8n8.x2.shared.b16 {%0,%1}, [%2];"
                             : "=r"(bf[nt][0]), "=r"(bf[nt][1])
                             : "r"(addr));
            }
            #pragma unroll
            for (int mt = 0; mt < 4; mt++)
                #pragma unroll
                for (int nt = 0; nt < 8; nt++) {
                    asm volatile(
                        "mma.sync.aligned.m16n8k16.row.col.f32.f16.f16.f32 "
                        "{%0,%1,%2,%3}, {%4,%5,%6,%7}, {%8,%9}, {%0,%1,%2,%3};\n"
                        : "+f"(acc[mt][nt][0]), "+f"(acc[mt][nt][1]),
                          "+f"(acc[mt][nt][2]), "+f"(acc[mt][nt][3])
                        : "r"(a[mt][0]), "r"(a[mt][1]), "r"(a[mt][2]), "r"(a[mt][3]),
                          "r"(bf[nt][0]), "r"(bf[nt][1]));
                }
        }
        __syncthreads();
        if (i + 2 < NCHUNK) load_chunk(i + 2, st);
    }

    #pragma unroll
    for (int mt = 0; mt < 4; mt++) {
        int mrow = m0 + wm + mt*16;
        #pragma unroll
        for (int nt = 0; nt < 8; nt++) {
            int n = n0 + wn + nt*8 + 2*tig;
            float bx = bp1[n], by = bp1[n+1];
            {
                size_t r = (size_t)(mrow + gid);
                float2 xv = *(const float2*)&x[r*BDIM + n];
                float2 o;
                o.x = acc[mt][nt][0] + xv.x + bx;
                o.y = acc[mt][nt][1] + xv.y + by;
                *(float2*)&g_x2[r*BDIM + n] = o;
            }
            {
                size_t r = (size_t)(mrow + gid + 8);
                float2 xv = *(const float2*)&x[r*BDIM + n];
                float2 o;
                o.x = acc[mt][nt][2] + xv.x + bx;
                o.y = acc[mt][nt][3] + xv.y + by;
                *(float2*)&g_x2[r*BDIM + n] = o;
            }
        }
    }
}

// ------ spool: LN-folded scores + sigmoid + attn + sums + pooling partials ------
#define RPB 32
#define SM_SPOOL (RPB*BDIM*4)            // 65536 bytes dynamic (x2 tile, fp32)
__global__ __launch_bounds__(256, 2) void k_spool(float* __restrict__ attn_out) {
    extern __shared__ float sx[];        // [RPB][512]
    __shared__ float sw[32][36];         // a*rstd, [c][s], padded for float4
    __shared__ float stats[RPB][2];
    int b = blockIdx.y, s0 = blockIdx.x * RPB;
    int tid = threadIdx.x, w = tid >> 5, lane = tid & 31;

    // stage fp32 x2 tile
    {
        const float4* xg = (const float4*)&g_x2[((size_t)b*SLEN + s0)*BDIM];
        float4* sx4 = (float4*)sx;
        #pragma unroll
        for (int i = 0; i < 16; i++)
            sx4[tid + i*256] = xg[tid + i*256];
    }
    __syncthreads();

    // stats: warp w -> rows 4w..4w+3 (lane-stride-32 slices, conflict-free)
    #pragma unroll
    for (int k = 0; k < 4; k++) {
        int r = w*4 + k;
        float sum = 0.f, sq = 0.f;
        #pragma unroll
        for (int i = 0; i < 16; i++) {
            float v = sx[r*BDIM + lane + 32*i];
            sum += v; sq += v*v;
        }
        #pragma unroll
        for (int off = 16; off; off >>= 1) {
            sum += __shfl_xor_sync(0xffffffffu, sum, off);
            sq  += __shfl_xor_sync(0xffffffffu, sq,  off);
        }
        if (lane == 0) {
            float mean = sum * (1.f/512.f);
            float var  = sq  * (1.f/512.f) - mean*mean;
            stats[r][0] = mean;
            stats[r][1] = rsqrtf(var + 1e-5f);
        }
    }

    // register-resident Wg slice: warp w owns c = 4w..4w+3 (lane-stride-32)
    float Wreg[4][16], Gs[4], Bs[4];
    #pragma unroll
    for (int j = 0; j < 4; j++) {
        int c = w*4 + j;
        #pragma unroll
        for (int i = 0; i < 16; i++)
            Wreg[j][i] = g_WqT[c*BDIM + lane + 32*i];
        Gs[j] = g_Gs[c];
        Bs[j] = g_Bs[c];
    }
    __syncthreads();

    float accA[4] = {0.f,0.f,0.f,0.f}, accM[4] = {0.f,0.f,0.f,0.f};
    for (int r = 0; r < RPB; r++) {
        float xv[16];
        #pragma unroll
        for (int i = 0; i < 16; i++) xv[i] = sx[r*BDIM + lane + 32*i];
        float v0 = 0.f, v1 = 0.f, v2 = 0.f, v3 = 0.f;
        #pragma unroll
        for (int i = 0; i < 16; i++) {
            v0 += xv[i]*Wreg[0][i];
            v1 += xv[i]*Wreg[1][i];
            v2 += xv[i]*Wreg[2][i];
            v3 += xv[i]*Wreg[3][i];
        }
        #pragma unroll
        for (int off = 16; off; off >>= 1) {
            v0 += __shfl_xor_sync(0xffffffffu, v0, off);
            v1 += __shfl_xor_sync(0xffffffffu, v1, off);
            v2 += __shfl_xor_sync(0xffffffffu, v2, off);
            v3 += __shfl_xor_sync(0xffffffffu, v3, off);
        }
        if (lane == 0) {
            float mean = stats[r][0], rstd = stats[r][1];
            float vv0 = rstd*v0 - rstd*mean*Gs[0] + Bs[0];
            float vv1 = rstd*v1 - rstd*mean*Gs[1] + Bs[1];
            float vv2 = rstd*v2 - rstd*mean*Gs[2] + Bs[2];
            float vv3 = rstd*v3 - rstd*mean*Gs[3] + Bs[3];
            float as[4];
            as[0] = 1.f/(1.f + expf(-(vv0 - LOGS)));
            as[1] = 1.f/(1.f + expf(-(vv1 - LOGS)));
            as[2] = 1.f/(1.f + expf(-(vv2 - LOGS)));
            as[3] = 1.f/(1.f + expf(-(vv3 - LOGS)));
            #pragma unroll
            for (int j = 0; j < 4; j++) {
                int c = w*4 + j;
                sw[c][r] = as[j] * rstd;
                int h = c & 15, n = c >> 4;
                attn_out[(((size_t)b*16 + h)*2 + n)*SLEN + s0 + r] = as[j];
                accA[j] += as[j];
                accM[j] += as[j] * rstd * mean;
            }
        }
    }
    if (lane == 0) {
        #pragma unroll
        for (int j = 0; j < 4; j++) {
            atomicAdd(&g_A[b*NC + w*4 + j],  accA[j]);
            atomicAdd(&g_Mw[b*NC + w*4 + j], accM[j]);
        }
    }
    __syncthreads();

    // pooling partials: P[c][d] = sum_s sw[c][s] * x2[s][d]  (Ppart, no atomics)
    float2 acc[32];
    #pragma unroll
    for (int c = 0; c < 32; c++) acc[c] = make_float2(0.f, 0.f);
    for (int s4 = 0; s4 < RPB; s4 += 4) {
        float a0[4], a1[4];
        #pragma unroll
        for (int k = 0; k < 4; k++) {
            a0[k] = sx[(s4+k)*BDIM + tid];
            a1[k] = sx[(s4+k)*BDIM + tid + 256];
        }
        #pragma unroll
        for (int c = 0; c < 32; c++) {
            float4 wv = *(const float4*)&sw[c][s4];
            acc[c].x += wv.x*a0[0] + wv.y*a0[1] + wv.z*a0[2] + wv.w*a0[3];
            acc[c].y += wv.x*a1[0] + wv.y*a1[1] + wv.z*a1[2] + wv.w*a1[3];
        }
    }
    size_t pbase = (((size_t)b*64 + blockIdx.x)*NC)*BDIM;
    #pragma unroll
    for (int c = 0; c < 32; c++) {
        g_Ppart[pbase + (size_t)c*BDIM + tid]       = acc[c].x;
        g_Ppart[pbase + (size_t)c*BDIM + tid + 256] = acc[c].y;
    }
}

// ---------------- combine partials -> pooled_xn ----------------
__global__ void k_pooled(const float* __restrict__ ln_g, const float* __restrict__ ln_b) {
    int c = blockIdx.x, b = blockIdx.y, d = threadIdx.x;
    float p = 0.f;
    #pragma unroll 16
    for (int sc = 0; sc < 64; sc++)
        p += g_Ppart[(((size_t)b*64 + sc)*NC + c)*BDIM + d];
    float val = ln_g[d]*(p - g_Mw[b*NC + c]) + ln_b[d]*g_A[b*NC + c];
    g_pooled[((size_t)b*NC + c)*BDIM + d] = val;
}

// ---------------- fused tail: ohead -> oproj -> head ----------------
__global__ __launch_bounds__(512) void k_tail(const float* __restrict__ Wkv,
                                              const float* __restrict__ Wproj,
                                              const float* __restrict__ bproj,
                                              const float* __restrict__ g2,
                                              const float* __restrict__ b2,
                                              const float* __restrict__ Wc1,
                                              const float* __restrict__ bc1,
                                              const float* __restrict__ Wc2,
                                              const float* __restrict__ bc2,
                                              float* __restrict__ out) {
    __shared__ float s1[BDIM];
    __shared__ float s2[BDIM];
    int b = blockIdx.x, n = blockIdx.y;
    int j = threadIdx.x;

    // phase 1: ohead[j] = pooled[b][n*16 + (j>>5)] . Wv[:, j]
    {
        int h = j >> 5;
        const float* pp = &g_pooled[((size_t)b*NC + n*16 + h)*BDIM];
        float acc = 0.f;
        #pragma unroll 16
        for (int d = 0; d < BDIM; d++)
            acc += pp[d] * Wkv[(size_t)d*1024 + 512 + j];
        s1[j] = acc;
    }
    __syncthreads();

    // phase 2: o[j] = s1 . Wproj[:, j] + bproj[j]
    {
        float acc = 0.f;
        #pragma unroll 16
        for (int d = 0; d < BDIM; d++)
            acc += s1[d] * Wproj[(size_t)d*BDIM + j];
        s2[j] = acc + bproj[j];
    }
    __syncthreads();

    // phase 3: head (LN2 + Wc1 + relu + Wc2)
    float v = s2[j];
    s1[j] = v; __syncthreads();
    for (int off = 256; off; off >>= 1) {
        if (j < off) s1[j] += s1[j + off];
        __syncthreads();
    }
    float mean = s1[0] * (1.f/512.f);
    __syncthreads();
    float dv = v - mean;
    s1[j] = dv*dv; __syncthreads();
    for (int off = 256; off; off >>= 1) {
        if (j < off) s1[j] += s1[j + off];
        __syncthreads();
    }
    float rstd = rsqrtf(s1[0]*(1.f/512.f) + 1e-5f);
    __syncthreads();
    s2[j] = dv*rstd*g2[j] + b2[j];
    __syncthreads();
    float hj = bc1[j];
    #pragma unroll 16
    for (int d = 0; d < BDIM; d++)
        hj += s2[d] * Wc1[(size_t)d*BDIM + j];
    hj = fmaxf(hj, 0.f);
    s1[j] = hj * Wc2[j];
    __syncthreads();
    for (int off = 256; off; off >>= 1) {
        if (j < off) s1[j] += s1[j + off];
        __syncthreads();
    }
    if (j == 0) out[b*2 + n] = s1[0] + bc2[0];
}

// ---------------- launch ----------------
extern "C" void kernel_launch(void* const* d_in, const int* in_sizes, int n_in,
                              void* d_out, int out_size) {
    const float* x      = (const float*)d_in[0];
    const float* wave1  = (const float*)d_in[1];
    const float* wave2  = (const float*)d_in[2];
    const float* wave3  = (const float*)d_in[3];
    const float* Wp1    = (const float*)d_in[4];
    const float* bp1    = (const float*)d_in[5];
    const float* cls    = (const float*)d_in[6];
    const float* ln1_g  = (const float*)d_in[7];
    const float* ln1_b  = (const float*)d_in[8];
    const float* Wq     = (const float*)d_in[9];
    const float* Wkv    = (const float*)d_in[10];
    const float* Wproj  = (const float*)d_in[11];
    const float* bproj  = (const float*)d_in[12];
    const float* ln2_g  = (const float*)d_in[13];
    const float* ln2_b  = (const float*)d_in[14];
    const float* Wc1    = (const float*)d_in[15];
    const float* bc1    = (const float*)d_in[16];
    const float* Wc2    = (const float*)d_in[17];
    const float* bc2    = (const float*)d_in[18];

    float* out  = (float*)d_out;
    float* attn = out + BATCH*2;   // logits [32,2] first, then attn [32,16,2,2048]

    static int smem_set = 0;
    if (!smem_set) {
        cudaFuncSetAttribute(k_conv,  cudaFuncAttributeMaxDynamicSharedMemorySize, SM_CONV);
        cudaFuncSetAttribute(k_gemm,  cudaFuncAttributeMaxDynamicSharedMemorySize, SM_GEMM);
        cudaFuncSetAttribute(k_spool, cudaFuncAttributeMaxDynamicSharedMemorySize, SM_SPOOL);
        smem_set = 1;
    }

    {
        dim3 g(BDIM/CDC, SLEN/CTS, BATCH);
        k_conv<<<g, 512, SM_CONV>>>(x, wave1, wave2, wave3);       // 1
    }
    k_prep<<<48, 512>>>(cls, Wq, Wkv, Wp1, ln1_g, ln1_b);          // 2
    {
        dim3 g(BDIM/GN, NROWS/GM);
        k_gemm<<<g, 256, SM_GEMM>>>(x, bp1);                       // 3
    }
    {
        dim3 g(SLEN/RPB, BATCH);                                   // (64, 32)
        k_spool<<<g, 256, SM_SPOOL>>>(attn);                       // 4  <- profiled
    }
    {
        dim3 g(NC, BATCH);
        k_pooled<<<g, BDIM>>>(ln1_g, ln1_b);                       // 5
    }
    {
        dim3 g(BATCH, 2);
        k_tail<<<g, BDIM>>>(Wkv, Wproj, bproj, ln2_g, ln2_b,
                            Wc1, bc1, Wc2, bc2, out);              // 6
    }
}

// round 13
// speedup vs baseline: 1.0075x; 1.0075x over previous
#include <cuda_runtime.h>
#include <cuda_fp16.h>
#include <math.h>
#include <stdint.h>

#define BDIM 512
#define SLEN 2048
#define BATCH 32
#define NROWS (BATCH*SLEN)
#define KS 19
#define NC 32                    // NCLS * H
#define LOGS 7.6246189861594f    // log(2048)

// ---------------- scratch (static device globals; no allocs) ----------------
__device__ float  g_WqT[NC*BDIM];                  // Wg = ln_g ⊙ WqEff, [c][d]
__device__ float  g_Gs[NC];                        // sum_d Wg[c][d]
__device__ float  g_Bs[NC];                        // sum_d ln_b[d]*W[c][d]
__device__ __half g_Wp1h[BDIM*BDIM];               // Wp1 transposed [n][k], fp16
__device__ __half g_posh[(size_t)NROWS*BDIM];      // conv output, fp16
__device__ float  g_x2[(size_t)NROWS*BDIM];        // x + pos@Wp1 + bp1
__device__ float  g_Ppart[(size_t)BATCH*64*NC*BDIM]; // pooling partials [b][chunk][c][d]
__device__ float  g_A[BATCH*NC];                   // sum attn
__device__ float  g_Mw[BATCH*NC];                  // sum attn*rstd*mean
__device__ float  g_pooled[BATCH*NC*BDIM];         // pooled xn [b][c][d]

// ---------------- helpers ----------------
__device__ __forceinline__ uint32_t s2u(const void* p) {
    uint32_t a;
    asm("{ .reg .u64 t; cvta.to.shared.u64 t, %1; cvt.u32.u64 %0, t; }" : "=r"(a) : "l"(p));
    return a;
}

// ---------------- conv (wavelet coefs fused, smem-tiled) ----------------
#define CTS 64
#define CDC 128
#define SM_CONV ((CTS+18)*CDC*4 + KS*CDC*4)     // 51712
__global__ __launch_bounds__(512) void k_conv(const float* __restrict__ x,
                                              const float* __restrict__ w1,
                                              const float* __restrict__ w2,
                                              const float* __restrict__ w3) {
    extern __shared__ char smc[];
    float (*tile)[CDC]  = (float(*)[CDC])smc;
    float (*scoef)[CDC] = (float(*)[CDC])(smc + (CTS+18)*CDC*4);
    int b  = blockIdx.z;
    int s0 = blockIdx.y * CTS;
    int d0 = blockIdx.x * CDC;
    int tid = threadIdx.x;

    const float C = 0.8673250705840776f;
    const float* ws[3] = {w1, w2, w3};
    for (int i = tid; i < KS*CDC; i += 512) {
        int t = i >> 7, d = i & (CDC-1);
        int dg = d0 + d;
        float xs = (float)(t - 9);
        float sum = 0.f;
        #pragma unroll
        for (int wv = 0; wv < 3; wv++) {
            float scale = ws[wv][dg];
            float shift = ws[wv][BDIM + dg];
            float u = (xs - shift) / scale;
            sum += C * (1.f - u*u) * expf(-0.5f*u*u) * rsqrtf(fabsf(scale));
        }
        scoef[t][d] = sum;
    }

    const int NV = (CTS + 18) * (CDC / 4);
    for (int i = tid; i < NV; i += 512) {
        int r = i / (CDC/4), c4 = i % (CDC/4);
        int s = s0 - 9 + r;
        float4 v = make_float4(0.f, 0.f, 0.f, 0.f);
        if (s >= 0 && s < SLEN)
            v = *(const float4*)&x[((size_t)b*SLEN + s)*BDIM + d0 + c4*4];
        *(float4*)&tile[r][c4*4] = v;
    }
    __syncthreads();

    int dL = tid & (CDC - 1);
    int g  = tid >> 7;
    float coef[KS];
    #pragma unroll
    for (int t = 0; t < KS; t++) coef[t] = scoef[t][dL];

    float acc[16];
    #pragma unroll
    for (int i = 0; i < 16; i++) acc[i] = 0.f;

    #pragma unroll
    for (int j = 0; j < 34; j++) {
        float v = tile[g*16 + j][dL];
        #pragma unroll
        for (int t = 0; t < KS; t++) {
            int s = j - t;
            if (s >= 0 && s < 16) acc[s] += v * coef[t];
        }
    }
    size_t base = ((size_t)b*SLEN + s0 + g*16)*BDIM + d0 + dL;
    #pragma unroll
    for (int i = 0; i < 16; i++)
        g_posh[base + (size_t)i*BDIM] = __float2half(acc[i]);
}

// ------- prep: Wg/Gs/Bs (blocks 0..31); Wp1 fp16 transpose (32..47) -------
__global__ __launch_bounds__(512) void k_prep(const float* __restrict__ cls,
                                              const float* __restrict__ Wq,
                                              const float* __restrict__ Wkv,
                                              const float* __restrict__ Wp1,
                                              const float* __restrict__ ln_g,
                                              const float* __restrict__ ln_b) {
    if (blockIdx.x < 32) {
        __shared__ float q[2][BDIM];
        __shared__ float red2[BDIM];
        int j = threadIdx.x;
        #pragma unroll
        for (int n = 0; n < 2; n++) {
            float acc = 0.f;
            #pragma unroll 16
            for (int d = 0; d < BDIM; d++)
                acc += __ldg(&cls[n*BDIM + d]) * Wq[(size_t)d*BDIM + j];
            q[n][j] = acc;
        }
        __syncthreads();
        int c = blockIdx.x, d = threadIdx.x;
        int n = c >> 4, h = c & 15;
        float acc = 0.f;
        #pragma unroll
        for (int hd = 0; hd < 32; hd++)
            acc += Wkv[(size_t)d*1024 + h*32 + hd] * q[n][h*32 + hd];
        acc *= 0.17677669529663689f;
        float wg = acc * ln_g[d];
        g_WqT[c*BDIM + d] = wg;
        red2[d] = wg;
        __syncthreads();
        for (int off = 256; off; off >>= 1) {
            if (d < off) red2[d] += red2[d + off];
            __syncthreads();
        }
        if (d == 0) g_Gs[c] = red2[0];
        __syncthreads();
        red2[d] = acc * ln_b[d];
        __syncthreads();
        for (int off = 256; off; off >>= 1) {
            if (d < off) red2[d] += red2[d + off];
            __syncthreads();
        }
        if (d == 0) g_Bs[c] = red2[0];
        if (d < BATCH) { g_A[d*NC + c] = 0.f; g_Mw[d*NC + c] = 0.f; }
    } else {
        int nb = (blockIdx.x - 32) * 32;
        int k = threadIdx.x;
        #pragma unroll
        for (int i = 0; i < 32; i++)
            g_Wp1h[(size_t)(nb + i)*BDIM + k] = __float2half(Wp1[(size_t)k*BDIM + nb + i]);
    }
}

// -------- x2 = x + pos @ Wp1 + bp1 (fp16 mma.sync + ldmatrix, 2-stage cp.async) --------
#define GM 128
#define GN 256
#define KCH 64
#define NCHUNK 8
#define AST 72
#define STG_H ((GM + GN) * AST)
#define SM_GEMM (2*STG_H*2)

__global__ __launch_bounds__(256) void k_gemm(const float* __restrict__ x,
                                              const float* __restrict__ bp1) {
    extern __shared__ __half smh[];
    uint32_t sb = s2u(smh);
    int tid  = threadIdx.x;
    int m0   = blockIdx.y * GM;
    int n0   = blockIdx.x * GN;
    int warp = tid >> 5, lane = tid & 31;
    int wm   = (warp & 1) * 64;
    int wn   = (warp >> 1) * 64;
    int gid  = lane >> 2, tig = lane & 3;

    float acc[4][8][4];
    #pragma unroll
    for (int i = 0; i < 4; i++)
        #pragma unroll
        for (int j = 0; j < 8; j++)
            #pragma unroll
            for (int r = 0; r < 4; r++) acc[i][j][r] = 0.f;

    auto load_chunk = [&](int ch, int st) {
        uint32_t ab = sb + (uint32_t)(st * STG_H) * 2u;
        uint32_t bb = ab + GM*AST*2u;
        const __half* As = g_posh + (size_t)m0 * BDIM + ch * KCH;
        #pragma unroll
        for (int it = 0; it < 4; it++) {
            int idx = tid + it * 256;
            int r = idx >> 3, c = idx & 7;
            uint32_t dst = ab + (uint32_t)(r*144 + c*16);
            const __half* src = As + (size_t)r * BDIM + c * 8;
            asm volatile("cp.async.cg.shared.global [%0], [%1], 16;" :: "r"(dst), "l"(src));
        }
        const __half* Bs = g_Wp1h + (size_t)n0 * BDIM + ch * KCH;
        #pragma unroll
        for (int it = 0; it < 8; it++) {
            int idx = tid + it * 256;
            int r = idx >> 3, c = idx & 7;
            uint32_t dst = bb + (uint32_t)(r*144 + c*16);
            const __half* src = Bs + (size_t)r * BDIM + c * 8;
            asm volatile("cp.async.cg.shared.global [%0], [%1], 16;" :: "r"(dst), "l"(src));
        }
        asm volatile("cp.async.commit_group;" ::: "memory");
    };

    load_chunk(0, 0);
    load_chunk(1, 1);

    for (int i = 0; i < NCHUNK; i++) {
        int st = i & 1;
        if (i >= NCHUNK - 1) asm volatile("cp.async.wait_group 0;" ::: "memory");
        else                 asm volatile("cp.async.wait_group 1;" ::: "memory");
        __syncthreads();

        uint32_t abase = sb + (uint32_t)(st * STG_H) * 2u;
        uint32_t bbase = abase + GM*AST*2u;
        int arow_off = (lane & 7) + ((lane >> 3) & 1) * 8;
        int acol_off = (lane >> 4) * 8;
        int brow_off = (lane & 7);
        int bcol_off = ((lane >> 3) & 1) * 8;

        #pragma unroll
        for (int ks = 0; ks < 4; ks++) {
            uint32_t a[4][4], bf[8][2];
            #pragma unroll
            for (int mt = 0; mt < 4; mt++) {
                int m = wm + mt*16 + arow_off;
                uint32_t addr = abase + (uint32_t)(m*144 + (ks*16 + acol_off)*2);
                asm volatile("ldmatrix.sync.aligned.m8n8.x4.shared.b16 {%0,%1,%2,%3}, [%4];"
                             : "=r"(a[mt][0]), "=r"(a[mt][1]), "=r"(a[mt][2]), "=r"(a[mt][3])
                             : "r"(addr));
            }
            #pragma unroll
            for (int nt = 0; nt < 8; nt++) {
                int n = wn + nt*8 + brow_off;
                uint32_t addr = bbase + (uint32_t)(n*144 + (ks*16 + bcol_off)*2);
                asm volatile("ldmatrix.sync.aligned.m8n8.x2.shared.b16 {%0,%1}, [%2];"
                             : "=r"(bf[nt][0]), "=r"(bf[nt][1])
                             : "r"(addr));
            }
            #pragma unroll
            for (int mt = 0; mt < 4; mt++)
                #pragma unroll
                for (int nt = 0; nt < 8; nt++) {
                    asm volatile(
                        "mma.sync.aligned.m16n8k16.row.col.f32.f16.f16.f32 "
                        "{%0,%1,%2,%3}, {%4,%5,%6,%7}, {%8,%9}, {%0,%1,%2,%3};\n"
                        : "+f"(acc[mt][nt][0]), "+f"(acc[mt][nt][1]),
                          "+f"(acc[mt][nt][2]), "+f"(acc[mt][nt][3])
                        : "r"(a[mt][0]), "r"(a[mt][1]), "r"(a[mt][2]), "r"(a[mt][3]),
                          "r"(bf[nt][0]), "r"(bf[nt][1]));
                }
        }
        __syncthreads();
        if (i + 2 < NCHUNK) load_chunk(i + 2, st);
    }

    #pragma unroll
    for (int mt = 0; mt < 4; mt++) {
        int mrow = m0 + wm + mt*16;
        #pragma unroll
        for (int nt = 0; nt < 8; nt++) {
            int n = n0 + wn + nt*8 + 2*tig;
            float bx = bp1[n], by = bp1[n+1];
            {
                size_t r = (size_t)(mrow + gid);
                float2 xv = *(const float2*)&x[r*BDIM + n];
                float2 o;
                o.x = acc[mt][nt][0] + xv.x + bx;
                o.y = acc[mt][nt][1] + xv.y + by;
                *(float2*)&g_x2[r*BDIM + n] = o;
            }
            {
                size_t r = (size_t)(mrow + gid + 8);
                float2 xv = *(const float2*)&x[r*BDIM + n];
                float2 o;
                o.x = acc[mt][nt][2] + xv.x + bx;
                o.y = acc[mt][nt][3] + xv.y + by;
                *(float2*)&g_x2[r*BDIM + n] = o;
            }
        }
    }
}

// ------ spool: LN-folded scores + sigmoid + attn + sums + pooling partials ------
#define RPB 32
#define SM_SPOOL (RPB*BDIM*4)            // 65536 bytes dynamic (x2 tile, fp32)
__global__ __launch_bounds__(256, 2) void k_spool(float* __restrict__ attn_out) {
    extern __shared__ float sx[];        // [RPB][512]
    __shared__ float sw[32][36];         // a*rstd, [c][s], padded for float4
    __shared__ float stats[RPB][2];
    int b = blockIdx.y, s0 = blockIdx.x * RPB;
    int tid = threadIdx.x, w = tid >> 5, lane = tid & 31;

    // stage fp32 x2 tile
    {
        const float4* xg = (const float4*)&g_x2[((size_t)b*SLEN + s0)*BDIM];
        float4* sx4 = (float4*)sx;
        #pragma unroll
        for (int i = 0; i < 16; i++)
            sx4[tid + i*256] = xg[tid + i*256];
    }
    __syncthreads();

    // stats: warp w -> rows 4w..4w+3 (lane-stride-32 slices, conflict-free)
    #pragma unroll
    for (int k = 0; k < 4; k++) {
        int r = w*4 + k;
        float sum = 0.f, sq = 0.f;
        #pragma unroll
        for (int i = 0; i < 16; i++) {
            float v = sx[r*BDIM + lane + 32*i];
            sum += v; sq += v*v;
        }
        #pragma unroll
        for (int off = 16; off; off >>= 1) {
            sum += __shfl_xor_sync(0xffffffffu, sum, off);
            sq  += __shfl_xor_sync(0xffffffffu, sq,  off);
        }
        if (lane == 0) {
            float mean = sum * (1.f/512.f);
            float var  = sq  * (1.f/512.f) - mean*mean;
            stats[r][0] = mean;
            stats[r][1] = rsqrtf(var + 1e-5f);
        }
    }

    // register-resident Wg slice: warp w owns c = 4w..4w+3 (lane-stride-32)
    float Wreg[4][16], Gs[4], Bs[4];
    #pragma unroll
    for (int j = 0; j < 4; j++) {
        int c = w*4 + j;
        #pragma unroll
        for (int i = 0; i < 16; i++)
            Wreg[j][i] = g_WqT[c*BDIM + lane + 32*i];
        Gs[j] = g_Gs[c];
        Bs[j] = g_Bs[c];
    }
    __syncthreads();

    float accA[4] = {0.f,0.f,0.f,0.f}, accM[4] = {0.f,0.f,0.f,0.f};
    for (int r = 0; r < RPB; r++) {
        float xv[16];
        #pragma unroll
        for (int i = 0; i < 16; i++) xv[i] = sx[r*BDIM + lane + 32*i];
        float v0 = 0.f, v1 = 0.f, v2 = 0.f, v3 = 0.f;
        #pragma unroll
        for (int i = 0; i < 16; i++) {
            v0 += xv[i]*Wreg[0][i];
            v1 += xv[i]*Wreg[1][i];
            v2 += xv[i]*Wreg[2][i];
            v3 += xv[i]*Wreg[3][i];
        }
        #pragma unroll
        for (int off = 16; off; off >>= 1) {
            v0 += __shfl_xor_sync(0xffffffffu, v0, off);
            v1 += __shfl_xor_sync(0xffffffffu, v1, off);
            v2 += __shfl_xor_sync(0xffffffffu, v2, off);
            v3 += __shfl_xor_sync(0xffffffffu, v3, off);
        }
        if (lane == 0) {
            float mean = stats[r][0], rstd = stats[r][1];
            float vv0 = rstd*v0 - rstd*mean*Gs[0] + Bs[0];
            float vv1 = rstd*v1 - rstd*mean*Gs[1] + Bs[1];
            float vv2 = rstd*v2 - rstd*mean*Gs[2] + Bs[2];
            float vv3 = rstd*v3 - rstd*mean*Gs[3] + Bs[3];
            float as[4];
            as[0] = 1.f/(1.f + expf(-(vv0 - LOGS)));
            as[1] = 1.f/(1.f + expf(-(vv1 - LOGS)));
            as[2] = 1.f/(1.f + expf(-(vv2 - LOGS)));
            as[3] = 1.f/(1.f + expf(-(vv3 - LOGS)));
            #pragma unroll
            for (int j = 0; j < 4; j++) {
                int c = w*4 + j;
                sw[c][r] = as[j] * rstd;
                int h = c & 15, n = c >> 4;
                attn_out[(((size_t)b*16 + h)*2 + n)*SLEN + s0 + r] = as[j];
                accA[j] += as[j];
                accM[j] += as[j] * rstd * mean;
            }
        }
    }
    if (lane == 0) {
        #pragma unroll
        for (int j = 0; j < 4; j++) {
            atomicAdd(&g_A[b*NC + w*4 + j],  accA[j]);
            atomicAdd(&g_Mw[b*NC + w*4 + j], accM[j]);
        }
    }
    __syncthreads();

    // pooling partials: P[c][d] = sum_s sw[c][s] * x2[s][d]  (Ppart, no atomics)
    float2 acc[32];
    #pragma unroll
    for (int c = 0; c < 32; c++) acc[c] = make_float2(0.f, 0.f);
    for (int s4 = 0; s4 < RPB; s4 += 4) {
        float a0[4], a1[4];
        #pragma unroll
        for (int k = 0; k < 4; k++) {
            a0[k] = sx[(s4+k)*BDIM + tid];
            a1[k] = sx[(s4+k)*BDIM + tid + 256];
        }
        #pragma unroll
        for (int c = 0; c < 32; c++) {
            float4 wv = *(const float4*)&sw[c][s4];
            acc[c].x += wv.x*a0[0] + wv.y*a0[1] + wv.z*a0[2] + wv.w*a0[3];
            acc[c].y += wv.x*a1[0] + wv.y*a1[1] + wv.z*a1[2] + wv.w*a1[3];
        }
    }
    size_t pbase = (((size_t)b*64 + blockIdx.x)*NC)*BDIM;
    #pragma unroll
    for (int c = 0; c < 32; c++) {
        g_Ppart[pbase + (size_t)c*BDIM + tid]       = acc[c].x;
        g_Ppart[pbase + (size_t)c*BDIM + tid + 256] = acc[c].y;
    }
}

// ---------------- combine partials -> pooled_xn ----------------
__global__ void k_pooled(const float* __restrict__ ln_g, const float* __restrict__ ln_b) {
    int c = blockIdx.x, b = blockIdx.y, d = threadIdx.x;
    float p = 0.f;
    #pragma unroll 16
    for (int sc = 0; sc < 64; sc++)
        p += g_Ppart[(((size_t)b*64 + sc)*NC + c)*BDIM + d];
    float val = ln_g[d]*(p - g_Mw[b*NC + c]) + ln_b[d]*g_A[b*NC + c];
    g_pooled[((size_t)b*NC + c)*BDIM + d] = val;
}

// ---------------- fused tail: ohead -> oproj -> head ----------------
__global__ __launch_bounds__(512) void k_tail(const float* __restrict__ Wkv,
                                              const float* __restrict__ Wproj,
                                              const float* __restrict__ bproj,
                                              const float* __restrict__ g2,
                                              const float* __restrict__ b2,
                                              const float* __restrict__ Wc1,
                                              const float* __restrict__ bc1,
                                              const float* __restrict__ Wc2,
                                              const float* __restrict__ bc2,
                                              float* __restrict__ out) {
    __shared__ float s1[BDIM];
    __shared__ float s2[BDIM];
    int b = blockIdx.x, n = blockIdx.y;
    int j = threadIdx.x;

    // phase 1: ohead[j] = pooled[b][n*16 + (j>>5)] . Wv[:, j]
    {
        int h = j >> 5;
        const float* pp = &g_pooled[((size_t)b*NC + n*16 + h)*BDIM];
        float acc = 0.f;
        #pragma unroll 16
        for (int d = 0; d < BDIM; d++)
            acc += pp[d] * Wkv[(size_t)d*1024 + 512 + j];
        s1[j] = acc;
    }
    __syncthreads();

    // phase 2: o[j] = s1 . Wproj[:, j] + bproj[j]
    {
        float acc = 0.f;
        #pragma unroll 16
        for (int d = 0; d < BDIM; d++)
            acc += s1[d] * Wproj[(size_t)d*BDIM + j];
        s2[j] = acc + bproj[j];
    }
    __syncthreads();

    // phase 3: head (LN2 + Wc1 + relu + Wc2)
    float v = s2[j];
    s1[j] = v; __syncthreads();
    for (int off = 256; off; off >>= 1) {
        if (j < off) s1[j] += s1[j + off];
        __syncthreads();
    }
    float mean = s1[0] * (1.f/512.f);
    __syncthreads();
    float dv = v - mean;
    s1[j] = dv*dv; __syncthreads();
    for (int off = 256; off; off >>= 1) {
        if (j < off) s1[j] += s1[j + off];
        __syncthreads();
    }
    float rstd = rsqrtf(s1[0]*(1.f/512.f) + 1e-5f);
    __syncthreads();
    s2[j] = dv*rstd*g2[j] + b2[j];
    __syncthreads();
    float hj = bc1[j];
    #pragma unroll 16
    for (int d = 0; d < BDIM; d++)
        hj += s2[d] * Wc1[(size_t)d*BDIM + j];
    hj = fmaxf(hj, 0.f);
    s1[j] = hj * Wc2[j];
    __syncthreads();
    for (int off = 256; off; off >>= 1) {
        if (j < off) s1[j] += s1[j + off];
        __syncthreads();
    }
    if (j == 0) out[b*2 + n] = s1[0] + bc2[0];
}

// ---------------- launch ----------------
extern "C" void kernel_launch(void* const* d_in, const int* in_sizes, int n_in,
                              void* d_out, int out_size) {
    const float* x      = (const float*)d_in[0];
    const float* wave1  = (const float*)d_in[1];
    const float* wave2  = (const float*)d_in[2];
    const float* wave3  = (const float*)d_in[3];
    const float* Wp1    = (const float*)d_in[4];
    const float* bp1    = (const float*)d_in[5];
    const float* cls    = (const float*)d_in[6];
    const float* ln1_g  = (const float*)d_in[7];
    const float* ln1_b  = (const float*)d_in[8];
    const float* Wq     = (const float*)d_in[9];
    const float* Wkv    = (const float*)d_in[10];
    const float* Wproj  = (const float*)d_in[11];
    const float* bproj  = (const float*)d_in[12];
    const float* ln2_g  = (const float*)d_in[13];
    const float* ln2_b  = (const float*)d_in[14];
    const float* Wc1    = (const float*)d_in[15];
    const float* bc1    = (const float*)d_in[16];
    const float* Wc2    = (const float*)d_in[17];
    const float* bc2    = (const float*)d_in[18];

    float* out  = (float*)d_out;
    float* attn = out + BATCH*2;   // logits [32,2] first, then attn [32,16,2,2048]

    static int smem_set = 0;
    if (!smem_set) {
        cudaFuncSetAttribute(k_conv,  cudaFuncAttributeMaxDynamicSharedMemorySize, SM_CONV);
        cudaFuncSetAttribute(k_gemm,  cudaFuncAttributeMaxDynamicSharedMemorySize, SM_GEMM);
        cudaFuncSetAttribute(k_spool, cudaFuncAttributeMaxDynamicSharedMemorySize, SM_SPOOL);
        smem_set = 1;
    }

    {
        dim3 g(BDIM/CDC, SLEN/CTS, BATCH);
        k_conv<<<g, 512, SM_CONV>>>(x, wave1, wave2, wave3);       // 1
    }
    k_prep<<<48, 512>>>(cls, Wq, Wkv, Wp1, ln1_g, ln1_b);          // 2
    {
        dim3 g(BDIM/GN, NROWS/GM);
        k_gemm<<<g, 256, SM_GEMM>>>(x, bp1);                       // 3
    }
    {
        dim3 g(SLEN/RPB, BATCH);                                   // (64, 32)
        k_spool<<<g, 256, SM_SPOOL>>>(attn);                       // 4  <- profiled
    }
    {
        dim3 g(NC, BATCH);
        k_pooled<<<g, BDIM>>>(ln1_g, ln1_b);                       // 5
    }
    {
        dim3 g(BATCH, 2);
        k_tail<<<g, BDIM>>>(Wkv, Wproj, bproj, ln2_g, ln2_b,
                            Wc1, bc1, Wc2, bc2, out);              // 6
    }
}

// round 14
// speedup vs baseline: 1.0334x; 1.0258x over previous
#include <cuda_runtime.h>
#include <cuda_fp16.h>
#include <math.h>
#include <stdint.h>

#define BDIM 512
#define SLEN 2048
#define BATCH 32
#define NROWS (BATCH*SLEN)
#define KS 19
#define NC 32                    // NCLS * H
#define LOGS 7.6246189861594f    // log(2048)

// ---------------- scratch (static device globals; no allocs) ----------------
__device__ float  g_WqT[NC*BDIM];                  // Wg = ln_g ⊙ WqEff, [c][d]
__device__ float  g_Gs[NC];                        // sum_d Wg[c][d]
__device__ float  g_Bs[NC];                        // sum_d ln_b[d]*W[c][d]
__device__ __half g_Wp1h[BDIM*BDIM];               // Wp1 transposed [n][k], fp16
__device__ __half g_posh[(size_t)NROWS*BDIM];      // conv output, fp16
__device__ float  g_x2[(size_t)NROWS*BDIM];        // x + pos@Wp1 + bp1
__device__ float  g_Ppart[(size_t)BATCH*64*NC*BDIM]; // pooling partials [b][chunk][c][d]
__device__ float  g_A[BATCH*NC];                   // sum attn
__device__ float  g_Mw[BATCH*NC];                  // sum attn*rstd*mean
__device__ float  g_pooled[BATCH*NC*BDIM];         // pooled xn [b][c][d]

// ---------------- helpers ----------------
__device__ __forceinline__ uint32_t s2u(const void* p) {
    uint32_t a;
    asm("{ .reg .u64 t; cvta.to.shared.u64 t, %1; cvt.u32.u64 %0, t; }" : "=r"(a) : "l"(p));
    return a;
}

// ---------------- conv (wavelet coefs fused, smem-tiled) ----------------
#define CTS 64
#define CDC 128
#define SM_CONV ((CTS+18)*CDC*4 + KS*CDC*4)     // 51712
__global__ __launch_bounds__(512) void k_conv(const float* __restrict__ x,
                                              const float* __restrict__ w1,
                                              const float* __restrict__ w2,
                                              const float* __restrict__ w3) {
    extern __shared__ char smc[];
    float (*tile)[CDC]  = (float(*)[CDC])smc;
    float (*scoef)[CDC] = (float(*)[CDC])(smc + (CTS+18)*CDC*4);
    int b  = blockIdx.z;
    int s0 = blockIdx.y * CTS;
    int d0 = blockIdx.x * CDC;
    int tid = threadIdx.x;

    const float C = 0.8673250705840776f;
    const float* ws[3] = {w1, w2, w3};
    for (int i = tid; i < KS*CDC; i += 512) {
        int t = i >> 7, d = i & (CDC-1);
        int dg = d0 + d;
        float xs = (float)(t - 9);
        float sum = 0.f;
        #pragma unroll
        for (int wv = 0; wv < 3; wv++) {
            float scale = ws[wv][dg];
            float shift = ws[wv][BDIM + dg];
            float u = (xs - shift) / scale;
            sum += C * (1.f - u*u) * expf(-0.5f*u*u) * rsqrtf(fabsf(scale));
        }
        scoef[t][d] = sum;
    }

    const int NV = (CTS + 18) * (CDC / 4);
    for (int i = tid; i < NV; i += 512) {
        int r = i / (CDC/4), c4 = i % (CDC/4);
        int s = s0 - 9 + r;
        float4 v = make_float4(0.f, 0.f, 0.f, 0.f);
        if (s >= 0 && s < SLEN)
            v = *(const float4*)&x[((size_t)b*SLEN + s)*BDIM + d0 + c4*4];
        *(float4*)&tile[r][c4*4] = v;
    }
    __syncthreads();

    int dL = tid & (CDC - 1);
    int g  = tid >> 7;
    float coef[KS];
    #pragma unroll
    for (int t = 0; t < KS; t++) coef[t] = scoef[t][dL];

    float acc[16];
    #pragma unroll
    for (int i = 0; i < 16; i++) acc[i] = 0.f;

    #pragma unroll
    for (int j = 0; j < 34; j++) {
        float v = tile[g*16 + j][dL];
        #pragma unroll
        for (int t = 0; t < KS; t++) {
            int s = j - t;
            if (s >= 0 && s < 16) acc[s] += v * coef[t];
        }
    }
    size_t base = ((size_t)b*SLEN + s0 + g*16)*BDIM + d0 + dL;
    #pragma unroll
    for (int i = 0; i < 16; i++)
        g_posh[base + (size_t)i*BDIM] = __float2half(acc[i]);
}

// ------- prep: Wg/Gs/Bs (blocks 0..31); Wp1 fp16 transpose (32..47) -------
__global__ __launch_bounds__(512) void k_prep(const float* __restrict__ cls,
                                              const float* __restrict__ Wq,
                                              const float* __restrict__ Wkv,
                                              const float* __restrict__ Wp1,
                                              const float* __restrict__ ln_g,
                                              const float* __restrict__ ln_b) {
    if (blockIdx.x < 32) {
        __shared__ float q[2][BDIM];
        __shared__ float red2[BDIM];
        int j = threadIdx.x;
        #pragma unroll
        for (int n = 0; n < 2; n++) {
            float acc = 0.f;
            #pragma unroll 16
            for (int d = 0; d < BDIM; d++)
                acc += __ldg(&cls[n*BDIM + d]) * Wq[(size_t)d*BDIM + j];
            q[n][j] = acc;
        }
        __syncthreads();
        int c = blockIdx.x, d = threadIdx.x;
        int n = c >> 4, h = c & 15;
        float acc = 0.f;
        #pragma unroll
        for (int hd = 0; hd < 32; hd++)
            acc += Wkv[(size_t)d*1024 + h*32 + hd] * q[n][h*32 + hd];
        acc *= 0.17677669529663689f;
        float wg = acc * ln_g[d];
        g_WqT[c*BDIM + d] = wg;
        red2[d] = wg;
        __syncthreads();
        for (int off = 256; off; off >>= 1) {
            if (d < off) red2[d] += red2[d + off];
            __syncthreads();
        }
        if (d == 0) g_Gs[c] = red2[0];
        __syncthreads();
        red2[d] = acc * ln_b[d];
        __syncthreads();
        for (int off = 256; off; off >>= 1) {
            if (d < off) red2[d] += red2[d + off];
            __syncthreads();
        }
        if (d == 0) g_Bs[c] = red2[0];
        if (d < BATCH) { g_A[d*NC + c] = 0.f; g_Mw[d*NC + c] = 0.f; }
    } else {
        int nb = (blockIdx.x - 32) * 32;
        int k = threadIdx.x;
        #pragma unroll
        for (int i = 0; i < 32; i++)
            g_Wp1h[(size_t)(nb + i)*BDIM + k] = __float2half(Wp1[(size_t)k*BDIM + nb + i]);
    }
}

// -------- x2 = x + pos @ Wp1 + bp1 (fp16 mma.sync + ldmatrix, 2-stage cp.async) --------
#define GM 128
#define GN 256
#define KCH 64
#define NCHUNK 8
#define AST 72
#define STG_H ((GM + GN) * AST)
#define SM_GEMM (2*STG_H*2)

__global__ __launch_bounds__(256) void k_gemm(const float* __restrict__ x,
                                              const float* __restrict__ bp1) {
    extern __shared__ __half smh[];
    uint32_t sb = s2u(smh);
    int tid  = threadIdx.x;
    int m0   = blockIdx.y * GM;
    int n0   = blockIdx.x * GN;
    int warp = tid >> 5, lane = tid & 31;
    int wm   = (warp & 1) * 64;
    int wn   = (warp >> 1) * 64;
    int gid  = lane >> 2, tig = lane & 3;

    float acc[4][8][4];
    #pragma unroll
    for (int i = 0; i < 4; i++)
        #pragma unroll
        for (int j = 0; j < 8; j++)
            #pragma unroll
            for (int r = 0; r < 4; r++) acc[i][j][r] = 0.f;

    auto load_chunk = [&](int ch, int st) {
        uint32_t ab = sb + (uint32_t)(st * STG_H) * 2u;
        uint32_t bb = ab + GM*AST*2u;
        const __half* As = g_posh + (size_t)m0 * BDIM + ch * KCH;
        #pragma unroll
        for (int it = 0; it < 4; it++) {
            int idx = tid + it * 256;
            int r = idx >> 3, c = idx & 7;
            uint32_t dst = ab + (uint32_t)(r*144 + c*16);
            const __half* src = As + (size_t)r * BDIM + c * 8;
            asm volatile("cp.async.cg.shared.global [%0], [%1], 16;" :: "r"(dst), "l"(src));
        }
        const __half* Bs = g_Wp1h + (size_t)n0 * BDIM + ch * KCH;
        #pragma unroll
        for (int it = 0; it < 8; it++) {
            int idx = tid + it * 256;
            int r = idx >> 3, c = idx & 7;
            uint32_t dst = bb + (uint32_t)(r*144 + c*16);
            const __half* src = Bs + (size_t)r * BDIM + c * 8;
            asm volatile("cp.async.cg.shared.global [%0], [%1], 16;" :: "r"(dst), "l"(src));
        }
        asm volatile("cp.async.commit_group;" ::: "memory");
    };

    load_chunk(0, 0);
    load_chunk(1, 1);

    for (int i = 0; i < NCHUNK; i++) {
        int st = i & 1;
        if (i >= NCHUNK - 1) asm volatile("cp.async.wait_group 0;" ::: "memory");
        else                 asm volatile("cp.async.wait_group 1;" ::: "memory");
        __syncthreads();

        uint32_t abase = sb + (uint32_t)(st * STG_H) * 2u;
        uint32_t bbase = abase + GM*AST*2u;
        int arow_off = (lane & 7) + ((lane >> 3) & 1) * 8;
        int acol_off = (lane >> 4) * 8;
        int brow_off = (lane & 7);
        int bcol_off = ((lane >> 3) & 1) * 8;

        #pragma unroll
        for (int ks = 0; ks < 4; ks++) {
            uint32_t a[4][4], bf[8][2];
            #pragma unroll
            for (int mt = 0; mt < 4; mt++) {
                int m = wm + mt*16 + arow_off;
                uint32_t addr = abase + (uint32_t)(m*144 + (ks*16 + acol_off)*2);
                asm volatile("ldmatrix.sync.aligned.m8n8.x4.shared.b16 {%0,%1,%2,%3}, [%4];"
                             : "=r"(a[mt][0]), "=r"(a[mt][1]), "=r"(a[mt][2]), "=r"(a[mt][3])
                             : "r"(addr));
            }
            #pragma unroll
            for (int nt = 0; nt < 8; nt++) {
                int n = wn + nt*8 + brow_off;
                uint32_t addr = bbase + (uint32_t)(n*144 + (ks*16 + bcol_off)*2);
                asm volatile("ldmatrix.sync.aligned.m8n8.x2.shared.b16 {%0,%1}, [%2];"
                             : "=r"(bf[nt][0]), "=r"(bf[nt][1])
                             : "r"(addr));
            }
            #pragma unroll
            for (int mt = 0; mt < 4; mt++)
                #pragma unroll
                for (int nt = 0; nt < 8; nt++) {
                    asm volatile(
                        "mma.sync.aligned.m16n8k16.row.col.f32.f16.f16.f32 "
                        "{%0,%1,%2,%3}, {%4,%5,%6,%7}, {%8,%9}, {%0,%1,%2,%3};\n"
                        : "+f"(acc[mt][nt][0]), "+f"(acc[mt][nt][1]),
                          "+f"(acc[mt][nt][2]), "+f"(acc[mt][nt][3])
                        : "r"(a[mt][0]), "r"(a[mt][1]), "r"(a[mt][2]), "r"(a[mt][3]),
                          "r"(bf[nt][0]), "r"(bf[nt][1]));
                }
        }
        __syncthreads();
        if (i + 2 < NCHUNK) load_chunk(i + 2, st);
    }

    #pragma unroll
    for (int mt = 0; mt < 4; mt++) {
        int mrow = m0 + wm + mt*16;
        #pragma unroll
        for (int nt = 0; nt < 8; nt++) {
            int n = n0 + wn + nt*8 + 2*tig;
            float bx = bp1[n], by = bp1[n+1];
            {
                size_t r = (size_t)(mrow + gid);
                float2 xv = *(const float2*)&x[r*BDIM + n];
                float2 o;
                o.x = acc[mt][nt][0] + xv.x + bx;
                o.y = acc[mt][nt][1] + xv.y + by;
                *(float2*)&g_x2[r*BDIM + n] = o;
            }
            {
                size_t r = (size_t)(mrow + gid + 8);
                float2 xv = *(const float2*)&x[r*BDIM + n];
                float2 o;
                o.x = acc[mt][nt][2] + xv.x + bx;
                o.y = acc[mt][nt][3] + xv.y + by;
                *(float2*)&g_x2[r*BDIM + n] = o;
            }
        }
    }
}

// ------ spool: LN-folded scores + sigmoid + attn + sums + tensor-core pooling ------
#define RPB 32
#define XHS 520                              // fp16 tile row stride (halves)
#define SM_SPOOL (RPB*BDIM*4 + RPB*XHS*2)    // 65536 + 33280 = 98816
__global__ __launch_bounds__(256, 2) void k_spool(float* __restrict__ attn_out) {
    extern __shared__ char smem_raw[];
    float*  sx  = (float*)smem_raw;                       // [RPB][512] fp32
    __half* sxh = (__half*)(smem_raw + RPB*BDIM*4);       // [RPB][XHS] fp16
    __shared__ __half swh[32][40];                        // a*rstd fp16, [c][s]
    __shared__ float stats[RPB][2];
    int b = blockIdx.y, s0 = blockIdx.x * RPB;
    int tid = threadIdx.x, w = tid >> 5, lane = tid & 31;

    // stage x2: fp32 for scores/stats, fp16 for pooling MMA
    {
        const float4* xg = (const float4*)&g_x2[((size_t)b*SLEN + s0)*BDIM];
        float4* sx4 = (float4*)sx;
        #pragma unroll
        for (int i = 0; i < 16; i++) {
            int idx = tid + i*256;
            float4 v = xg[idx];
            sx4[idx] = v;
            int s = idx >> 7, dq = (idx & 127) * 4;
            __half2 h0 = __floats2half2_rn(v.x, v.y);
            __half2 h1 = __floats2half2_rn(v.z, v.w);
            uint32_t u0 = *reinterpret_cast<uint32_t*>(&h0);
            uint32_t u1 = *reinterpret_cast<uint32_t*>(&h1);
            *reinterpret_cast<uint2*>(&sxh[(size_t)s*XHS + dq]) = make_uint2(u0, u1);
        }
    }
    __syncthreads();

    // stats: warp w -> rows 4w..4w+3 (lane-stride-32 slices, conflict-free)
    #pragma unroll
    for (int k = 0; k < 4; k++) {
        int r = w*4 + k;
        float sum = 0.f, sq = 0.f;
        #pragma unroll
        for (int i = 0; i < 16; i++) {
            float v = sx[r*BDIM + lane + 32*i];
            sum += v; sq += v*v;
        }
        #pragma unroll
        for (int off = 16; off; off >>= 1) {
            sum += __shfl_xor_sync(0xffffffffu, sum, off);
            sq  += __shfl_xor_sync(0xffffffffu, sq,  off);
        }
        if (lane == 0) {
            float mean = sum * (1.f/512.f);
            float var  = sq  * (1.f/512.f) - mean*mean;
            stats[r][0] = mean;
            stats[r][1] = rsqrtf(var + 1e-5f);
        }
    }

    // register-resident Wg slice: warp w owns c = 4w..4w+3 (lane-stride-32)
    float Wreg[4][16], Gs[4], Bs[4];
    #pragma unroll
    for (int j = 0; j < 4; j++) {
        int c = w*4 + j;
        #pragma unroll
        for (int i = 0; i < 16; i++)
            Wreg[j][i] = g_WqT[c*BDIM + lane + 32*i];
        Gs[j] = g_Gs[c];
        Bs[j] = g_Bs[c];
    }
    __syncthreads();

    float accA[4] = {0.f,0.f,0.f,0.f}, accM[4] = {0.f,0.f,0.f,0.f};
    for (int r = 0; r < RPB; r++) {
        float xv[16];
        #pragma unroll
        for (int i = 0; i < 16; i++) xv[i] = sx[r*BDIM + lane + 32*i];
        float v0 = 0.f, v1 = 0.f, v2 = 0.f, v3 = 0.f;
        #pragma unroll
        for (int i = 0; i < 16; i++) {
            v0 += xv[i]*Wreg[0][i];
            v1 += xv[i]*Wreg[1][i];
            v2 += xv[i]*Wreg[2][i];
            v3 += xv[i]*Wreg[3][i];
        }
        #pragma unroll
        for (int off = 16; off; off >>= 1) {
            v0 += __shfl_xor_sync(0xffffffffu, v0, off);
            v1 += __shfl_xor_sync(0xffffffffu, v1, off);
            v2 += __shfl_xor_sync(0xffffffffu, v2, off);
            v3 += __shfl_xor_sync(0xffffffffu, v3, off);
        }
        if (lane == 0) {
            float mean = stats[r][0], rstd = stats[r][1];
            float vv0 = rstd*v0 - rstd*mean*Gs[0] + Bs[0];
            float vv1 = rstd*v1 - rstd*mean*Gs[1] + Bs[1];
            float vv2 = rstd*v2 - rstd*mean*Gs[2] + Bs[2];
            float vv3 = rstd*v3 - rstd*mean*Gs[3] + Bs[3];
            float as[4];
            as[0] = 1.f/(1.f + expf(-(vv0 - LOGS)));
            as[1] = 1.f/(1.f + expf(-(vv1 - LOGS)));
            as[2] = 1.f/(1.f + expf(-(vv2 - LOGS)));
            as[3] = 1.f/(1.f + expf(-(vv3 - LOGS)));
            #pragma unroll
            for (int j = 0; j < 4; j++) {
                int c = w*4 + j;
                swh[c][r] = __float2half(as[j] * rstd);
                int h = c & 15, n = c >> 4;
                attn_out[(((size_t)b*16 + h)*2 + n)*SLEN + s0 + r] = as[j];
                accA[j] += as[j];
                accM[j] += as[j] * rstd * mean;
            }
        }
    }
    if (lane == 0) {
        #pragma unroll
        for (int j = 0; j < 4; j++) {
            atomicAdd(&g_A[b*NC + w*4 + j],  accA[j]);
            atomicAdd(&g_Mw[b*NC + w*4 + j], accM[j]);
        }
    }
    __syncthreads();

    // pooling via tensor cores: P[c][d] = sum_s swh[c][s] * sxh[s][d]
    // per warp: m=32 (c), n=64 (d range w*64..+63), k=32 (s)
    {
        int n0 = w * 64;
        uint32_t swb = s2u(&swh[0][0]);
        uint32_t xhb = s2u(sxh);
        int arow = (lane & 7) + ((lane >> 3) & 1) * 8;
        int acol = (lane >> 4) * 8;
        int krow = lane & 15;

        float pacc[2][8][4];
        #pragma unroll
        for (int mt = 0; mt < 2; mt++)
            #pragma unroll
            for (int nt = 0; nt < 8; nt++)
                #pragma unroll
                for (int q = 0; q < 4; q++) pacc[mt][nt][q] = 0.f;

        #pragma unroll
        for (int kt = 0; kt < 2; kt++) {
            uint32_t afr[2][4];
            #pragma unroll
            for (int mt = 0; mt < 2; mt++) {
                uint32_t addr = swb + (uint32_t)((mt*16 + arow)*40 + kt*16 + acol) * 2u;
                asm volatile("ldmatrix.sync.aligned.m8n8.x4.shared.b16 {%0,%1,%2,%3}, [%4];"
                             : "=r"(afr[mt][0]), "=r"(afr[mt][1]), "=r"(afr[mt][2]), "=r"(afr[mt][3])
                             : "r"(addr));
            }
            uint32_t bfr[8][2];
            #pragma unroll
            for (int nt = 0; nt < 8; nt++) {
                uint32_t addr = xhb + (uint32_t)((kt*16 + krow)*XHS + n0 + nt*8) * 2u;
                asm volatile("ldmatrix.sync.aligned.m8n8.x2.trans.shared.b16 {%0,%1}, [%2];"
                             : "=r"(bfr[nt][0]), "=r"(bfr[nt][1])
                             : "r"(addr));
            }
            #pragma unroll
            for (int mt = 0; mt < 2; mt++)
                #pragma unroll
                for (int nt = 0; nt < 8; nt++) {
                    asm volatile(
                        "mma.sync.aligned.m16n8k16.row.col.f32.f16.f16.f32 "
                        "{%0,%1,%2,%3}, {%4,%5,%6,%7}, {%8,%9}, {%0,%1,%2,%3};\n"
                        : "+f"(pacc[mt][nt][0]), "+f"(pacc[mt][nt][1]),
                          "+f"(pacc[mt][nt][2]), "+f"(pacc[mt][nt][3])
                        : "r"(afr[mt][0]), "r"(afr[mt][1]), "r"(afr[mt][2]), "r"(afr[mt][3]),
                          "r"(bfr[nt][0]), "r"(bfr[nt][1]));
                }
        }

        int gid = lane >> 2, tig = lane & 3;
        size_t pbase = (((size_t)b*64 + blockIdx.x)*NC)*BDIM;
        #pragma unroll
        for (int mt = 0; mt < 2; mt++) {
            #pragma unroll
            for (int nt = 0; nt < 8; nt++) {
                int c0 = mt*16 + gid;
                int dcol = n0 + nt*8 + 2*tig;
                float2 lo = make_float2(pacc[mt][nt][0], pacc[mt][nt][1]);
                float2 hi = make_float2(pacc[mt][nt][2], pacc[mt][nt][3]);
                *(float2*)&g_Ppart[pbase + (size_t)c0*BDIM + dcol]       = lo;
                *(float2*)&g_Ppart[pbase + (size_t)(c0+8)*BDIM + dcol]   = hi;
            }
        }
    }
}

// ---------------- combine partials -> pooled_xn ----------------
__global__ void k_pooled(const float* __restrict__ ln_g, const float* __restrict__ ln_b) {
    int c = blockIdx.x, b = blockIdx.y, d = threadIdx.x;
    float p = 0.f;
    #pragma unroll 16
    for (int sc = 0; sc < 64; sc++)
        p += g_Ppart[(((size_t)b*64 + sc)*NC + c)*BDIM + d];
    float val = ln_g[d]*(p - g_Mw[b*NC + c]) + ln_b[d]*g_A[b*NC + c];
    g_pooled[((size_t)b*NC + c)*BDIM + d] = val;
}

// ---------------- fused tail: ohead -> oproj -> head ----------------
__global__ __launch_bounds__(512) void k_tail(const float* __restrict__ Wkv,
                                              const float* __restrict__ Wproj,
                                              const float* __restrict__ bproj,
                                              const float* __restrict__ g2,
                                              const float* __restrict__ b2,
                                              const float* __restrict__ Wc1,
                                              const float* __restrict__ bc1,
                                              const float* __restrict__ Wc2,
                                              const float* __restrict__ bc2,
                                              float* __restrict__ out) {
    __shared__ float s1[BDIM];
    __shared__ float s2[BDIM];
    int b = blockIdx.x, n = blockIdx.y;
    int j = threadIdx.x;

    {
        int h = j >> 5;
        const float* pp = &g_pooled[((size_t)b*NC + n*16 + h)*BDIM];
        float acc = 0.f;
        #pragma unroll 16
        for (int d = 0; d < BDIM; d++)
            acc += pp[d] * Wkv[(size_t)d*1024 + 512 + j];
        s1[j] = acc;
    }
    __syncthreads();

    {
        float acc = 0.f;
        #pragma unroll 16
        for (int d = 0; d < BDIM; d++)
            acc += s1[d] * Wproj[(size_t)d*BDIM + j];
        s2[j] = acc + bproj[j];
    }
    __syncthreads();

    float v = s2[j];
    s1[j] = v; __syncthreads();
    for (int off = 256; off; off >>= 1) {
        if (j < off) s1[j] += s1[j + off];
        __syncthreads();
    }
    float mean = s1[0] * (1.f/512.f);
    __syncthreads();
    float dv = v - mean;
    s1[j] = dv*dv; __syncthreads();
    for (int off = 256; off; off >>= 1) {
        if (j < off) s1[j] += s1[j + off];
        __syncthreads();
    }
    float rstd = rsqrtf(s1[0]*(1.f/512.f) + 1e-5f);
    __syncthreads();
    s2[j] = dv*rstd*g2[j] + b2[j];
    __syncthreads();
    float hj = bc1[j];
    #pragma unroll 16
    for (int d = 0; d < BDIM; d++)
        hj += s2[d] * Wc1[(size_t)d*BDIM + j];
    hj = fmaxf(hj, 0.f);
    s1[j] = hj * Wc2[j];
    __syncthreads();
    for (int off = 256; off; off >>= 1) {
        if (j < off) s1[j] += s1[j + off];
        __syncthreads();
    }
    if (j == 0) out[b*2 + n] = s1[0] + bc2[0];
}

// ---------------- launch ----------------
extern "C" void kernel_launch(void* const* d_in, const int* in_sizes, int n_in,
                              void* d_out, int out_size) {
    const float* x      = (const float*)d_in[0];
    const float* wave1  = (const float*)d_in[1];
    const float* wave2  = (const float*)d_in[2];
    const float* wave3  = (const float*)d_in[3];
    const float* Wp1    = (const float*)d_in[4];
    const float* bp1    = (const float*)d_in[5];
    const float* cls    = (const float*)d_in[6];
    const float* ln1_g  = (const float*)d_in[7];
    const float* ln1_b  = (const float*)d_in[8];
    const float* Wq     = (const float*)d_in[9];
    const float* Wkv    = (const float*)d_in[10];
    const float* Wproj  = (const float*)d_in[11];
    const float* bproj  = (const float*)d_in[12];
    const float* ln2_g  = (const float*)d_in[13];
    const float* ln2_b  = (const float*)d_in[14];
    const float* Wc1    = (const float*)d_in[15];
    const float* bc1    = (const float*)d_in[16];
    const float* Wc2    = (const float*)d_in[17];
    const float* bc2    = (const float*)d_in[18];

    float* out  = (float*)d_out;
    float* attn = out + BATCH*2;   // logits [32,2] first, then attn [32,16,2,2048]

    static int smem_set = 0;
    if (!smem_set) {
        cudaFuncSetAttribute(k_conv,  cudaFuncAttributeMaxDynamicSharedMemorySize, SM_CONV);
        cudaFuncSetAttribute(k_gemm,  cudaFuncAttributeMaxDynamicSharedMemorySize, SM_GEMM);
        cudaFuncSetAttribute(k_spool, cudaFuncAttributeMaxDynamicSharedMemorySize, SM_SPOOL);
        smem_set = 1;
    }

    {
        dim3 g(BDIM/CDC, SLEN/CTS, BATCH);
        k_conv<<<g, 512, SM_CONV>>>(x, wave1, wave2, wave3);       // 1
    }
    k_prep<<<48, 512>>>(cls, Wq, Wkv, Wp1, ln1_g, ln1_b);          // 2
    {
        dim3 g(BDIM/GN, NROWS/GM);
        k_gemm<<<g, 256, SM_GEMM>>>(x, bp1);                       // 3
    }
    {
        dim3 g(SLEN/RPB, BATCH);                                   // (64, 32)
        k_spool<<<g, 256, SM_SPOOL>>>(attn);                       // 4  <- profiled
    }
    {
        dim3 g(NC, BATCH);
        k_pooled<<<g, BDIM>>>(ln1_g, ln1_b);                       // 5
    }
    {
        dim3 g(BATCH, 2);
        k_tail<<<g, BDIM>>>(Wkv, Wproj, bproj, ln2_g, ln2_b,
                            Wc1, bc1, Wc2, bc2, out);              // 6
    }
}

// round 15
// speedup vs baseline: 1.0428x; 1.0091x over previous
#include <cuda_runtime.h>
#include <cuda_fp16.h>
#include <math.h>
#include <stdint.h>

#define BDIM 512
#define SLEN 2048
#define BATCH 32
#define NROWS (BATCH*SLEN)
#define KS 19
#define NC 32                    // NCLS * H
#define LOGS 7.6246189861594f    // log(2048)

// ---------------- scratch (static device globals; no allocs) ----------------
__device__ float  g_WqT[NC*BDIM];                  // Wg = ln_g ⊙ WqEff, [c][d]
__device__ float  g_Gs[NC];                        // sum_d Wg[c][d]
__device__ float  g_Bs[NC];                        // sum_d ln_b[d]*W[c][d]
__device__ __half g_Wp1h[BDIM*BDIM];               // Wp1 transposed [n][k], fp16
__device__ __half g_posh[(size_t)NROWS*BDIM];      // conv output, fp16
__device__ float  g_x2[(size_t)NROWS*BDIM];        // x + pos@Wp1 + bp1
__device__ float  g_Ppart[(size_t)BATCH*64*NC*BDIM]; // pooling partials [b][chunk][c][d]
__device__ float  g_A[BATCH*NC];                   // sum attn
__device__ float  g_Mw[BATCH*NC];                  // sum attn*rstd*mean
__device__ float  g_pooled[BATCH*NC*BDIM];         // pooled xn [b][c][d]

// ---------------- helpers ----------------
__device__ __forceinline__ uint32_t s2u(const void* p) {
    uint32_t a;
    asm("{ .reg .u64 t; cvta.to.shared.u64 t, %1; cvt.u32.u64 %0, t; }" : "=r"(a) : "l"(p));
    return a;
}

// ---------------- conv (wavelet coefs fused, smem-tiled) ----------------
#define CTS 64
#define CDC 128
#define SM_CONV ((CTS+18)*CDC*4 + KS*CDC*4)     // 51712
__global__ __launch_bounds__(512) void k_conv(const float* __restrict__ x,
                                              const float* __restrict__ w1,
                                              const float* __restrict__ w2,
                                              const float* __restrict__ w3) {
    extern __shared__ char smc[];
    float (*tile)[CDC]  = (float(*)[CDC])smc;
    float (*scoef)[CDC] = (float(*)[CDC])(smc + (CTS+18)*CDC*4);
    int b  = blockIdx.z;
    int s0 = blockIdx.y * CTS;
    int d0 = blockIdx.x * CDC;
    int tid = threadIdx.x;

    const float C = 0.8673250705840776f;
    const float* ws[3] = {w1, w2, w3};
    for (int i = tid; i < KS*CDC; i += 512) {
        int t = i >> 7, d = i & (CDC-1);
        int dg = d0 + d;
        float xs = (float)(t - 9);
        float sum = 0.f;
        #pragma unroll
        for (int wv = 0; wv < 3; wv++) {
            float scale = ws[wv][dg];
            float shift = ws[wv][BDIM + dg];
            float u = (xs - shift) / scale;
            sum += C * (1.f - u*u) * expf(-0.5f*u*u) * rsqrtf(fabsf(scale));
        }
        scoef[t][d] = sum;
    }

    const int NV = (CTS + 18) * (CDC / 4);
    for (int i = tid; i < NV; i += 512) {
        int r = i / (CDC/4), c4 = i % (CDC/4);
        int s = s0 - 9 + r;
        float4 v = make_float4(0.f, 0.f, 0.f, 0.f);
        if (s >= 0 && s < SLEN)
            v = *(const float4*)&x[((size_t)b*SLEN + s)*BDIM + d0 + c4*4];
        *(float4*)&tile[r][c4*4] = v;
    }
    __syncthreads();

    int dL = tid & (CDC - 1);
    int g  = tid >> 7;
    float coef[KS];
    #pragma unroll
    for (int t = 0; t < KS; t++) coef[t] = scoef[t][dL];

    float acc[16];
    #pragma unroll
    for (int i = 0; i < 16; i++) acc[i] = 0.f;

    #pragma unroll
    for (int j = 0; j < 34; j++) {
        float v = tile[g*16 + j][dL];
        #pragma unroll
        for (int t = 0; t < KS; t++) {
            int s = j - t;
            if (s >= 0 && s < 16) acc[s] += v * coef[t];
        }
    }
    size_t base = ((size_t)b*SLEN + s0 + g*16)*BDIM + d0 + dL;
    #pragma unroll
    for (int i = 0; i < 16; i++)
        g_posh[base + (size_t)i*BDIM] = __float2half(acc[i]);
}

// ------- prep: Wg/Gs/Bs (blocks 0..31); Wp1 fp16 transpose (32..47) -------
__global__ __launch_bounds__(512) void k_prep(const float* __restrict__ cls,
                                              const float* __restrict__ Wq,
                                              const float* __restrict__ Wkv,
                                              const float* __restrict__ Wp1,
                                              const float* __restrict__ ln_g,
                                              const float* __restrict__ ln_b) {
    if (blockIdx.x < 32) {
        __shared__ float q[2][BDIM];
        __shared__ float red2[BDIM];
        int j = threadIdx.x;
        #pragma unroll
        for (int n = 0; n < 2; n++) {
            float acc = 0.f;
            #pragma unroll 16
            for (int d = 0; d < BDIM; d++)
                acc += __ldg(&cls[n*BDIM + d]) * Wq[(size_t)d*BDIM + j];
            q[n][j] = acc;
        }
        __syncthreads();
        int c = blockIdx.x, d = threadIdx.x;
        int n = c >> 4, h = c & 15;
        float acc = 0.f;
        #pragma unroll
        for (int hd = 0; hd < 32; hd++)
            acc += Wkv[(size_t)d*1024 + h*32 + hd] * q[n][h*32 + hd];
        acc *= 0.17677669529663689f;
        float wg = acc * ln_g[d];
        g_WqT[c*BDIM + d] = wg;
        red2[d] = wg;
        __syncthreads();
        for (int off = 256; off; off >>= 1) {
            if (d < off) red2[d] += red2[d + off];
            __syncthreads();
        }
        if (d == 0) g_Gs[c] = red2[0];
        __syncthreads();
        red2[d] = acc * ln_b[d];
        __syncthreads();
        for (int off = 256; off; off >>= 1) {
            if (d < off) red2[d] += red2[d + off];
            __syncthreads();
        }
        if (d == 0) g_Bs[c] = red2[0];
        if (d < BATCH) { g_A[d*NC + c] = 0.f; g_Mw[d*NC + c] = 0.f; }
    } else {
        int nb = (blockIdx.x - 32) * 32;
        int k = threadIdx.x;
        #pragma unroll
        for (int i = 0; i < 32; i++)
            g_Wp1h[(size_t)(nb + i)*BDIM + k] = __float2half(Wp1[(size_t)k*BDIM + nb + i]);
    }
}

// -------- x2 = x + pos @ Wp1 + bp1 (fp16 mma.sync + ldmatrix, 2-stage cp.async) --------
#define GM 128
#define GN 256
#define KCH 64
#define NCHUNK 8
#define AST 72
#define STG_H ((GM + GN) * AST)
#define SM_GEMM (2*STG_H*2)

__global__ __launch_bounds__(256) void k_gemm(const float* __restrict__ x,
                                              const float* __restrict__ bp1) {
    extern __shared__ __half smh[];
    uint32_t sb = s2u(smh);
    int tid  = threadIdx.x;
    int m0   = blockIdx.y * GM;
    int n0   = blockIdx.x * GN;
    int warp = tid >> 5, lane = tid & 31;
    int wm   = (warp & 1) * 64;
    int wn   = (warp >> 1) * 64;
    int gid  = lane >> 2, tig = lane & 3;

    float acc[4][8][4];
    #pragma unroll
    for (int i = 0; i < 4; i++)
        #pragma unroll
        for (int j = 0; j < 8; j++)
            #pragma unroll
            for (int r = 0; r < 4; r++) acc[i][j][r] = 0.f;

    auto load_chunk = [&](int ch, int st) {
        uint32_t ab = sb + (uint32_t)(st * STG_H) * 2u;
        uint32_t bb = ab + GM*AST*2u;
        const __half* As = g_posh + (size_t)m0 * BDIM + ch * KCH;
        #pragma unroll
        for (int it = 0; it < 4; it++) {
            int idx = tid + it * 256;
            int r = idx >> 3, c = idx & 7;
            uint32_t dst = ab + (uint32_t)(r*144 + c*16);
            const __half* src = As + (size_t)r * BDIM + c * 8;
            asm volatile("cp.async.cg.shared.global [%0], [%1], 16;" :: "r"(dst), "l"(src));
        }
        const __half* Bs = g_Wp1h + (size_t)n0 * BDIM + ch * KCH;
        #pragma unroll
        for (int it = 0; it < 8; it++) {
            int idx = tid + it * 256;
            int r = idx >> 3, c = idx & 7;
            uint32_t dst = bb + (uint32_t)(r*144 + c*16);
            const __half* src = Bs + (size_t)r * BDIM + c * 8;
            asm volatile("cp.async.cg.shared.global [%0], [%1], 16;" :: "r"(dst), "l"(src));
        }
        asm volatile("cp.async.commit_group;" ::: "memory");
    };

    load_chunk(0, 0);
    load_chunk(1, 1);

    for (int i = 0; i < NCHUNK; i++) {
        int st = i & 1;
        if (i >= NCHUNK - 1) asm volatile("cp.async.wait_group 0;" ::: "memory");
        else                 asm volatile("cp.async.wait_group 1;" ::: "memory");
        __syncthreads();

        uint32_t abase = sb + (uint32_t)(st * STG_H) * 2u;
        uint32_t bbase = abase + GM*AST*2u;
        int arow_off = (lane & 7) + ((lane >> 3) & 1) * 8;
        int acol_off = (lane >> 4) * 8;
        int brow_off = (lane & 7);
        int bcol_off = ((lane >> 3) & 1) * 8;

        #pragma unroll
        for (int ks = 0; ks < 4; ks++) {
            uint32_t a[4][4], bf[8][2];
            #pragma unroll
            for (int mt = 0; mt < 4; mt++) {
                int m = wm + mt*16 + arow_off;
                uint32_t addr = abase + (uint32_t)(m*144 + (ks*16 + acol_off)*2);
                asm volatile("ldmatrix.sync.aligned.m8n8.x4.shared.b16 {%0,%1,%2,%3}, [%4];"
                             : "=r"(a[mt][0]), "=r"(a[mt][1]), "=r"(a[mt][2]), "=r"(a[mt][3])
                             : "r"(addr));
            }
            #pragma unroll
            for (int nt = 0; nt < 8; nt++) {
                int n = wn + nt*8 + brow_off;
                uint32_t addr = bbase + (uint32_t)(n*144 + (ks*16 + bcol_off)*2);
                asm volatile("ldmatrix.sync.aligned.m8n8.x2.shared.b16 {%0,%1}, [%2];"
                             : "=r"(bf[nt][0]), "=r"(bf[nt][1])
                             : "r"(addr));
            }
            #pragma unroll
            for (int mt = 0; mt < 4; mt++)
                #pragma unroll
                for (int nt = 0; nt < 8; nt++) {
                    asm volatile(
                        "mma.sync.aligned.m16n8k16.row.col.f32.f16.f16.f32 "
                        "{%0,%1,%2,%3}, {%4,%5,%6,%7}, {%8,%9}, {%0,%1,%2,%3};\n"
                        : "+f"(acc[mt][nt][0]), "+f"(acc[mt][nt][1]),
                          "+f"(acc[mt][nt][2]), "+f"(acc[mt][nt][3])
                        : "r"(a[mt][0]), "r"(a[mt][1]), "r"(a[mt][2]), "r"(a[mt][3]),
                          "r"(bf[nt][0]), "r"(bf[nt][1]));
                }
        }
        __syncthreads();
        if (i + 2 < NCHUNK) load_chunk(i + 2, st);
    }

    #pragma unroll
    for (int mt = 0; mt < 4; mt++) {
        int mrow = m0 + wm + mt*16;
        #pragma unroll
        for (int nt = 0; nt < 8; nt++) {
            int n = n0 + wn + nt*8 + 2*tig;
            float bx = bp1[n], by = bp1[n+1];
            {
                size_t r = (size_t)(mrow + gid);
                float2 xv = *(const float2*)&x[r*BDIM + n];
                float2 o;
                o.x = acc[mt][nt][0] + xv.x + bx;
                o.y = acc[mt][nt][1] + xv.y + by;
                *(float2*)&g_x2[r*BDIM + n] = o;
            }
            {
                size_t r = (size_t)(mrow + gid + 8);
                float2 xv = *(const float2*)&x[r*BDIM + n];
                float2 o;
                o.x = acc[mt][nt][2] + xv.x + bx;
                o.y = acc[mt][nt][3] + xv.y + by;
                *(float2*)&g_x2[r*BDIM + n] = o;
            }
        }
    }
}

// ------ spool: LN-folded scores + sigmoid + attn + sums + tensor-core pooling ------
#define RPB 32
#define XHS 520                              // fp16 tile row stride (halves)
#define SM_SPOOL (RPB*BDIM*4 + RPB*XHS*2)    // 65536 + 33280 = 98816
__global__ __launch_bounds__(256, 2) void k_spool(float* __restrict__ attn_out) {
    extern __shared__ char smem_raw[];
    float*  sx  = (float*)smem_raw;                       // [RPB][512] fp32
    __half* sxh = (__half*)(smem_raw + RPB*BDIM*4);       // [RPB][XHS] fp16
    __shared__ __half swh[32][40];                        // a*rstd fp16, [c][s]
    __shared__ float stats[RPB][2];
    int b = blockIdx.y, s0 = blockIdx.x * RPB;
    int tid = threadIdx.x, w = tid >> 5, lane = tid & 31;

    // stage x2: fp32 for scores/stats, fp16 for pooling MMA
    {
        const float4* xg = (const float4*)&g_x2[((size_t)b*SLEN + s0)*BDIM];
        float4* sx4 = (float4*)sx;
        #pragma unroll
        for (int i = 0; i < 16; i++) {
            int idx = tid + i*256;
            float4 v = xg[idx];
            sx4[idx] = v;
            int s = idx >> 7, dq = (idx & 127) * 4;
            __half2 h0 = __floats2half2_rn(v.x, v.y);
            __half2 h1 = __floats2half2_rn(v.z, v.w);
            uint32_t u0 = *reinterpret_cast<uint32_t*>(&h0);
            uint32_t u1 = *reinterpret_cast<uint32_t*>(&h1);
            *reinterpret_cast<uint2*>(&sxh[(size_t)s*XHS + dq]) = make_uint2(u0, u1);
        }
    }
    __syncthreads();

    // stats: warp w -> rows 4w..4w+3 (lane-stride-32 slices, conflict-free)
    #pragma unroll
    for (int k = 0; k < 4; k++) {
        int r = w*4 + k;
        float sum = 0.f, sq = 0.f;
        #pragma unroll
        for (int i = 0; i < 16; i++) {
            float v = sx[r*BDIM + lane + 32*i];
            sum += v; sq += v*v;
        }
        #pragma unroll
        for (int off = 16; off; off >>= 1) {
            sum += __shfl_xor_sync(0xffffffffu, sum, off);
            sq  += __shfl_xor_sync(0xffffffffu, sq,  off);
        }
        if (lane == 0) {
            float mean = sum * (1.f/512.f);
            float var  = sq  * (1.f/512.f) - mean*mean;
            stats[r][0] = mean;
            stats[r][1] = rsqrtf(var + 1e-5f);
        }
    }

    // register-resident Wg slice: warp w owns c = 4w..4w+3 (lane-stride-32)
    float Wreg[4][16], Gs[4], Bs[4];
    #pragma unroll
    for (int j = 0; j < 4; j++) {
        int c = w*4 + j;
        #pragma unroll
        for (int i = 0; i < 16; i++)
            Wreg[j][i] = g_WqT[c*BDIM + lane + 32*i];
        Gs[j] = g_Gs[c];
        Bs[j] = g_Bs[c];
    }
    __syncthreads();

    float accA[4] = {0.f,0.f,0.f,0.f}, accM[4] = {0.f,0.f,0.f,0.f};
    for (int r = 0; r < RPB; r++) {
        float xv[16];
        #pragma unroll
        for (int i = 0; i < 16; i++) xv[i] = sx[r*BDIM + lane + 32*i];
        float v0 = 0.f, v1 = 0.f, v2 = 0.f, v3 = 0.f;
        #pragma unroll
        for (int i = 0; i < 16; i++) {
            v0 += xv[i]*Wreg[0][i];
            v1 += xv[i]*Wreg[1][i];
            v2 += xv[i]*Wreg[2][i];
            v3 += xv[i]*Wreg[3][i];
        }
        #pragma unroll
        for (int off = 16; off; off >>= 1) {
            v0 += __shfl_xor_sync(0xffffffffu, v0, off);
            v1 += __shfl_xor_sync(0xffffffffu, v1, off);
            v2 += __shfl_xor_sync(0xffffffffu, v2, off);
            v3 += __shfl_xor_sync(0xffffffffu, v3, off);
        }
        if (lane == 0) {
            float mean = stats[r][0], rstd = stats[r][1];
            float vv0 = rstd*v0 - rstd*mean*Gs[0] + Bs[0];
            float vv1 = rstd*v1 - rstd*mean*Gs[1] + Bs[1];
            float vv2 = rstd*v2 - rstd*mean*Gs[2] + Bs[2];
            float vv3 = rstd*v3 - rstd*mean*Gs[3] + Bs[3];
            float as[4];
            as[0] = 1.f/(1.f + expf(-(vv0 - LOGS)));
            as[1] = 1.f/(1.f + expf(-(vv1 - LOGS)));
            as[2] = 1.f/(1.f + expf(-(vv2 - LOGS)));
            as[3] = 1.f/(1.f + expf(-(vv3 - LOGS)));
            #pragma unroll
            for (int j = 0; j < 4; j++) {
                int c = w*4 + j;
                swh[c][r] = __float2half(as[j] * rstd);
                int h = c & 15, n = c >> 4;
                attn_out[(((size_t)b*16 + h)*2 + n)*SLEN + s0 + r] = as[j];
                accA[j] += as[j];
                accM[j] += as[j] * rstd * mean;
            }
        }
    }
    if (lane == 0) {
        #pragma unroll
        for (int j = 0; j < 4; j++) {
            atomicAdd(&g_A[b*NC + w*4 + j],  accA[j]);
            atomicAdd(&g_Mw[b*NC + w*4 + j], accM[j]);
        }
    }
    __syncthreads();

    // pooling via tensor cores: P[c][d] = sum_s swh[c][s] * sxh[s][d]
    // per warp: m=32 (c), n=64 (d range w*64..+63), k=32 (s)
    {
        int n0 = w * 64;
        uint32_t swb = s2u(&swh[0][0]);
        uint32_t xhb = s2u(sxh);
        int arow = (lane & 7) + ((lane >> 3) & 1) * 8;
        int acol = (lane >> 4) * 8;
        int krow = lane & 15;

        float pacc[2][8][4];
        #pragma unroll
        for (int mt = 0; mt < 2; mt++)
            #pragma unroll
            for (int nt = 0; nt < 8; nt++)
                #pragma unroll
                for (int q = 0; q < 4; q++) pacc[mt][nt][q] = 0.f;

        #pragma unroll
        for (int kt = 0; kt < 2; kt++) {
            uint32_t afr[2][4];
            #pragma unroll
            for (int mt = 0; mt < 2; mt++) {
                uint32_t addr = swb + (uint32_t)((mt*16 + arow)*40 + kt*16 + acol) * 2u;
                asm volatile("ldmatrix.sync.aligned.m8n8.x4.shared.b16 {%0,%1,%2,%3}, [%4];"
                             : "=r"(afr[mt][0]), "=r"(afr[mt][1]), "=r"(afr[mt][2]), "=r"(afr[mt][3])
                             : "r"(addr));
            }
            uint32_t bfr[8][2];
            #pragma unroll
            for (int nt = 0; nt < 8; nt++) {
                uint32_t addr = xhb + (uint32_t)((kt*16 + krow)*XHS + n0 + nt*8) * 2u;
                asm volatile("ldmatrix.sync.aligned.m8n8.x2.trans.shared.b16 {%0,%1}, [%2];"
                             : "=r"(bfr[nt][0]), "=r"(bfr[nt][1])
                             : "r"(addr));
            }
            #pragma unroll
            for (int mt = 0; mt < 2; mt++)
                #pragma unroll
                for (int nt = 0; nt < 8; nt++) {
                    asm volatile(
                        "mma.sync.aligned.m16n8k16.row.col.f32.f16.f16.f32 "
                        "{%0,%1,%2,%3}, {%4,%5,%6,%7}, {%8,%9}, {%0,%1,%2,%3};\n"
                        : "+f"(pacc[mt][nt][0]), "+f"(pacc[mt][nt][1]),
                          "+f"(pacc[mt][nt][2]), "+f"(pacc[mt][nt][3])
                        : "r"(afr[mt][0]), "r"(afr[mt][1]), "r"(afr[mt][2]), "r"(afr[mt][3]),
                          "r"(bfr[nt][0]), "r"(bfr[nt][1]));
                }
        }

        int gid = lane >> 2, tig = lane & 3;
        size_t pbase = (((size_t)b*64 + blockIdx.x)*NC)*BDIM;
        #pragma unroll
        for (int mt = 0; mt < 2; mt++) {
            #pragma unroll
            for (int nt = 0; nt < 8; nt++) {
                int c0 = mt*16 + gid;
                int dcol = n0 + nt*8 + 2*tig;
                float2 lo = make_float2(pacc[mt][nt][0], pacc[mt][nt][1]);
                float2 hi = make_float2(pacc[mt][nt][2], pacc[mt][nt][3]);
                *(float2*)&g_Ppart[pbase + (size_t)c0*BDIM + dcol]       = lo;
                *(float2*)&g_Ppart[pbase + (size_t)(c0+8)*BDIM + dcol]   = hi;
            }
        }
    }
}

// ---------------- combine partials -> pooled_xn ----------------
__global__ void k_pooled(const float* __restrict__ ln_g, const float* __restrict__ ln_b) {
    int c = blockIdx.x, b = blockIdx.y, d = threadIdx.x;
    float p = 0.f;
    #pragma unroll 16
    for (int sc = 0; sc < 64; sc++)
        p += g_Ppart[(((size_t)b*64 + sc)*NC + c)*BDIM + d];
    float val = ln_g[d]*(p - g_Mw[b*NC + c]) + ln_b[d]*g_A[b*NC + c];
    g_pooled[((size_t)b*NC + c)*BDIM + d] = val;
}

// ---------------- fused tail: ohead -> oproj -> head ----------------
__global__ __launch_bounds__(512) void k_tail(const float* __restrict__ Wkv,
                                              const float* __restrict__ Wproj,
                                              const float* __restrict__ bproj,
                                              const float* __restrict__ g2,
                                              const float* __restrict__ b2,
                                              const float* __restrict__ Wc1,
                                              const float* __restrict__ bc1,
                                              const float* __restrict__ Wc2,
                                              const float* __restrict__ bc2,
                                              float* __restrict__ out) {
    __shared__ float s1[BDIM];
    __shared__ float s2[BDIM];
    int b = blockIdx.x, n = blockIdx.y;
    int j = threadIdx.x;

    {
        int h = j >> 5;
        const float* pp = &g_pooled[((size_t)b*NC + n*16 + h)*BDIM];
        float acc = 0.f;
        #pragma unroll 16
        for (int d = 0; d < BDIM; d++)
            acc += pp[d] * Wkv[(size_t)d*1024 + 512 + j];
        s1[j] = acc;
    }
    __syncthreads();

    {
        float acc = 0.f;
        #pragma unroll 16
        for (int d = 0; d < BDIM; d++)
            acc += s1[d] * Wproj[(size_t)d*BDIM + j];
        s2[j] = acc + bproj[j];
    }
    __syncthreads();

    float v = s2[j];
    s1[j] = v; __syncthreads();
    for (int off = 256; off; off >>= 1) {
        if (j < off) s1[j] += s1[j + off];
        __syncthreads();
    }
    float mean = s1[0] * (1.f/512.f);
    __syncthreads();
    float dv = v - mean;
    s1[j] = dv*dv; __syncthreads();
    for (int off = 256; off; off >>= 1) {
        if (j < off) s1[j] += s1[j + off];
        __syncthreads();
    }
    float rstd = rsqrtf(s1[0]*(1.f/512.f) + 1e-5f);
    __syncthreads();
    s2[j] = dv*rstd*g2[j] + b2[j];
    __syncthreads();
    float hj = bc1[j];
    #pragma unroll 16
    for (int d = 0; d < BDIM; d++)
        hj += s2[d] * Wc1[(size_t)d*BDIM + j];
    hj = fmaxf(hj, 0.f);
    s1[j] = hj * Wc2[j];
    __syncthreads();
    for (int off = 256; off; off >>= 1) {
        if (j < off) s1[j] += s1[j + off];
        __syncthreads();
    }
    if (j == 0) out[b*2 + n] = s1[0] + bc2[0];
}

// ---------------- launch ----------------
extern "C" void kernel_launch(void* const* d_in, const int* in_sizes, int n_in,
                              void* d_out, int out_size) {
    const float* x      = (const float*)d_in[0];
    const float* wave1  = (const float*)d_in[1];
    const float* wave2  = (const float*)d_in[2];
    const float* wave3  = (const float*)d_in[3];
    const float* Wp1    = (const float*)d_in[4];
    const float* bp1    = (const float*)d_in[5];
    const float* cls    = (const float*)d_in[6];
    const float* ln1_g  = (const float*)d_in[7];
    const float* ln1_b  = (const float*)d_in[8];
    const float* Wq     = (const float*)d_in[9];
    const float* Wkv    = (const float*)d_in[10];
    const float* Wproj  = (const float*)d_in[11];
    const float* bproj  = (const float*)d_in[12];
    const float* ln2_g  = (const float*)d_in[13];
    const float* ln2_b  = (const float*)d_in[14];
    const float* Wc1    = (const float*)d_in[15];
    const float* bc1    = (const float*)d_in[16];
    const float* Wc2    = (const float*)d_in[17];
    const float* bc2    = (const float*)d_in[18];

    float* out  = (float*)d_out;
    float* attn = out + BATCH*2;   // logits [32,2] first, then attn [32,16,2,2048]

    static int smem_set = 0;
    if (!smem_set) {
        cudaFuncSetAttribute(k_conv,  cudaFuncAttributeMaxDynamicSharedMemorySize, SM_CONV);
        cudaFuncSetAttribute(k_gemm,  cudaFuncAttributeMaxDynamicSharedMemorySize, SM_GEMM);
        cudaFuncSetAttribute(k_spool, cudaFuncAttributeMaxDynamicSharedMemorySize, SM_SPOOL);
        smem_set = 1;
    }

    {
        dim3 g(BDIM/CDC, SLEN/CTS, BATCH);
        k_conv<<<g, 512, SM_CONV>>>(x, wave1, wave2, wave3);       // 1
    }
    k_prep<<<48, 512>>>(cls, Wq, Wkv, Wp1, ln1_g, ln1_b);          // 2
    {
        dim3 g(BDIM/GN, NROWS/GM);
        k_gemm<<<g, 256, SM_GEMM>>>(x, bp1);                       // 3
    }
    {
        dim3 g(SLEN/RPB, BATCH);                                   // (64, 32)
        k_spool<<<g, 256, SM_SPOOL>>>(attn);                       // 4  <- profiled
    }
    {
        dim3 g(NC, BATCH);
        k_pooled<<<g, BDIM>>>(ln1_g, ln1_b);                       // 5
    }
    {
        dim3 g(BATCH, 2);
        k_tail<<<g, BDIM>>>(Wkv, Wproj, bproj, ln2_g, ln2_b,
                            Wc1, bc1, Wc2, bc2, out);              // 6
    }
}

// round 16
// speedup vs baseline: 1.0429x; 1.0001x over previous
#include <cuda_runtime.h>
#include <cuda_fp16.h>
#include <math.h>
#include <stdint.h>

#define BDIM 512
#define SLEN 2048
#define BATCH 32
#define NROWS (BATCH*SLEN)
#define KS 19
#define NC 32                    // NCLS * H
#define LOGS 7.6246189861594f    // log(2048)

// ---------------- scratch (static device globals; no allocs) ----------------
__device__ float  g_WqT[NC*BDIM];                  // Wg = ln_g ⊙ WqEff, [c][d]
__device__ float  g_Gs[NC];                        // sum_d Wg[c][d]
__device__ float  g_Bs[NC];                        // sum_d ln_b[d]*W[c][d]
__device__ __half g_Wp1h[BDIM*BDIM];               // Wp1 transposed [n][k], fp16
__device__ __half g_posh[(size_t)NROWS*BDIM];      // conv output, fp16
__device__ float  g_x2[(size_t)NROWS*BDIM];        // x + pos@Wp1 + bp1
__device__ float  g_Ppart[(size_t)BATCH*64*NC*BDIM]; // pooling partials [b][chunk][c][d]
__device__ float  g_A[BATCH*NC];                   // sum attn
__device__ float  g_Mw[BATCH*NC];                  // sum attn*rstd*mean
__device__ float  g_pooled[BATCH*NC*BDIM];         // pooled xn [b][c][d]

// ---------------- helpers ----------------
__device__ __forceinline__ uint32_t s2u(const void* p) {
    uint32_t a;
    asm("{ .reg .u64 t; cvta.to.shared.u64 t, %1; cvt.u32.u64 %0, t; }" : "=r"(a) : "l"(p));
    return a;
}

// ---------------- conv (wavelet coefs fused, smem-tiled) ----------------
#define CTS 64
#define CDC 128
#define SM_CONV ((CTS+18)*CDC*4 + KS*CDC*4)     // 51712
__global__ __launch_bounds__(512) void k_conv(const float* __restrict__ x,
                                              const float* __restrict__ w1,
                                              const float* __restrict__ w2,
                                              const float* __restrict__ w3) {
    extern __shared__ char smc[];
    float (*tile)[CDC]  = (float(*)[CDC])smc;
    float (*scoef)[CDC] = (float(*)[CDC])(smc + (CTS+18)*CDC*4);
    int b  = blockIdx.z;
    int s0 = blockIdx.y * CTS;
    int d0 = blockIdx.x * CDC;
    int tid = threadIdx.x;

    const float C = 0.8673250705840776f;
    const float* ws[3] = {w1, w2, w3};
    for (int i = tid; i < KS*CDC; i += 512) {
        int t = i >> 7, d = i & (CDC-1);
        int dg = d0 + d;
        float xs = (float)(t - 9);
        float sum = 0.f;
        #pragma unroll
        for (int wv = 0; wv < 3; wv++) {
            float scale = ws[wv][dg];
            float shift = ws[wv][BDIM + dg];
            float u = (xs - shift) / scale;
            sum += C * (1.f - u*u) * expf(-0.5f*u*u) * rsqrtf(fabsf(scale));
        }
        scoef[t][d] = sum;
    }

    const int NV = (CTS + 18) * (CDC / 4);
    for (int i = tid; i < NV; i += 512) {
        int r = i / (CDC/4), c4 = i % (CDC/4);
        int s = s0 - 9 + r;
        float4 v = make_float4(0.f, 0.f, 0.f, 0.f);
        if (s >= 0 && s < SLEN)
            v = *(const float4*)&x[((size_t)b*SLEN + s)*BDIM + d0 + c4*4];
        *(float4*)&tile[r][c4*4] = v;
    }
    __syncthreads();

    int dL = tid & (CDC - 1);
    int g  = tid >> 7;
    float coef[KS];
    #pragma unroll
    for (int t = 0; t < KS; t++) coef[t] = scoef[t][dL];

    float acc[16];
    #pragma unroll
    for (int i = 0; i < 16; i++) acc[i] = 0.f;

    #pragma unroll
    for (int j = 0; j < 34; j++) {
        float v = tile[g*16 + j][dL];
        #pragma unroll
        for (int t = 0; t < KS; t++) {
            int s = j - t;
            if (s >= 0 && s < 16) acc[s] += v * coef[t];
        }
    }
    size_t base = ((size_t)b*SLEN + s0 + g*16)*BDIM + d0 + dL;
    #pragma unroll
    for (int i = 0; i < 16; i++)
        g_posh[base + (size_t)i*BDIM] = __float2half(acc[i]);
}

// ------- prep: Wg/Gs/Bs (blocks 0..31); Wp1 fp16 transpose (32..47) -------
__global__ __launch_bounds__(512) void k_prep(const float* __restrict__ cls,
                                              const float* __restrict__ Wq,
                                              const float* __restrict__ Wkv,
                                              const float* __restrict__ Wp1,
                                              const float* __restrict__ ln_g,
                                              const float* __restrict__ ln_b) {
    if (blockIdx.x < 32) {
        __shared__ float q[2][BDIM];
        __shared__ float red2[BDIM];
        int j = threadIdx.x;
        #pragma unroll
        for (int n = 0; n < 2; n++) {
            float acc = 0.f;
            #pragma unroll 16
            for (int d = 0; d < BDIM; d++)
                acc += __ldg(&cls[n*BDIM + d]) * Wq[(size_t)d*BDIM + j];
            q[n][j] = acc;
        }
        __syncthreads();
        int c = blockIdx.x, d = threadIdx.x;
        int n = c >> 4, h = c & 15;
        float acc = 0.f;
        #pragma unroll
        for (int hd = 0; hd < 32; hd++)
            acc += Wkv[(size_t)d*1024 + h*32 + hd] * q[n][h*32 + hd];
        acc *= 0.17677669529663689f;
        float wg = acc * ln_g[d];
        g_WqT[c*BDIM + d] = wg;
        red2[d] = wg;
        __syncthreads();
        for (int off = 256; off; off >>= 1) {
            if (d < off) red2[d] += red2[d + off];
            __syncthreads();
        }
        if (d == 0) g_Gs[c] = red2[0];
        __syncthreads();
        red2[d] = acc * ln_b[d];
        __syncthreads();
        for (int off = 256; off; off >>= 1) {
            if (d < off) red2[d] += red2[d + off];
            __syncthreads();
        }
        if (d == 0) g_Bs[c] = red2[0];
        if (d < BATCH) { g_A[d*NC + c] = 0.f; g_Mw[d*NC + c] = 0.f; }
    } else {
        int nb = (blockIdx.x - 32) * 32;
        int k = threadIdx.x;
        #pragma unroll
        for (int i = 0; i < 32; i++)
            g_Wp1h[(size_t)(nb + i)*BDIM + k] = __float2half(Wp1[(size_t)k*BDIM + nb + i]);
    }
}

// -------- x2 = x + pos @ Wp1 + bp1 (fp16 mma.sync + ldmatrix, 2-stage cp.async) --------
#define GM 128
#define GN 256
#define KCH 64
#define NCHUNK 8
#define AST 72
#define STG_H ((GM + GN) * AST)
#define SM_GEMM (2*STG_H*2)

__global__ __launch_bounds__(256) void k_gemm(const float* __restrict__ x,
                                              const float* __restrict__ bp1) {
    extern __shared__ __half smh[];
    uint32_t sb = s2u(smh);
    int tid  = threadIdx.x;
    int m0   = blockIdx.y * GM;
    int n0   = blockIdx.x * GN;
    int warp = tid >> 5, lane = tid & 31;
    int wm   = (warp & 1) * 64;
    int wn   = (warp >> 1) * 64;
    int gid  = lane >> 2, tig = lane & 3;

    float acc[4][8][4];
    #pragma unroll
    for (int i = 0; i < 4; i++)
        #pragma unroll
        for (int j = 0; j < 8; j++)
            #pragma unroll
            for (int r = 0; r < 4; r++) acc[i][j][r] = 0.f;

    auto load_chunk = [&](int ch, int st) {
        uint32_t ab = sb + (uint32_t)(st * STG_H) * 2u;
        uint32_t bb = ab + GM*AST*2u;
        const __half* As = g_posh + (size_t)m0 * BDIM + ch * KCH;
        #pragma unroll
        for (int it = 0; it < 4; it++) {
            int idx = tid + it * 256;
            int r = idx >> 3, c = idx & 7;
            uint32_t dst = ab + (uint32_t)(r*144 + c*16);
            const __half* src = As + (size_t)r * BDIM + c * 8;
            asm volatile("cp.async.cg.shared.global [%0], [%1], 16;" :: "r"(dst), "l"(src));
        }
        const __half* Bs = g_Wp1h + (size_t)n0 * BDIM + ch * KCH;
        #pragma unroll
        for (int it = 0; it < 8; it++) {
            int idx = tid + it * 256;
            int r = idx >> 3, c = idx & 7;
            uint32_t dst = bb + (uint32_t)(r*144 + c*16);
            const __half* src = Bs + (size_t)r * BDIM + c * 8;
            asm volatile("cp.async.cg.shared.global [%0], [%1], 16;" :: "r"(dst), "l"(src));
        }
        asm volatile("cp.async.commit_group;" ::: "memory");
    };

    load_chunk(0, 0);
    load_chunk(1, 1);

    for (int i = 0; i < NCHUNK; i++) {
        int st = i & 1;
        if (i >= NCHUNK - 1) asm volatile("cp.async.wait_group 0;" ::: "memory");
        else                 asm volatile("cp.async.wait_group 1;" ::: "memory");
        __syncthreads();

        uint32_t abase = sb + (uint32_t)(st * STG_H) * 2u;
        uint32_t bbase = abase + GM*AST*2u;
        int arow_off = (lane & 7) + ((lane >> 3) & 1) * 8;
        int acol_off = (lane >> 4) * 8;
        int brow_off = (lane & 7);
        int bcol_off = ((lane >> 3) & 1) * 8;

        #pragma unroll
        for (int ks = 0; ks < 4; ks++) {
            uint32_t a[4][4], bf[8][2];
            #pragma unroll
            for (int mt = 0; mt < 4; mt++) {
                int m = wm + mt*16 + arow_off;
                uint32_t addr = abase + (uint32_t)(m*144 + (ks*16 + acol_off)*2);
                asm volatile("ldmatrix.sync.aligned.m8n8.x4.shared.b16 {%0,%1,%2,%3}, [%4];"
                             : "=r"(a[mt][0]), "=r"(a[mt][1]), "=r"(a[mt][2]), "=r"(a[mt][3])
                             : "r"(addr));
            }
            #pragma unroll
            for (int nt = 0; nt < 8; nt++) {
                int n = wn + nt*8 + brow_off;
                uint32_t addr = bbase + (uint32_t)(n*144 + (ks*16 + bcol_off)*2);
                asm volatile("ldmatrix.sync.aligned.m8n8.x2.shared.b16 {%0,%1}, [%2];"
                             : "=r"(bf[nt][0]), "=r"(bf[nt][1])
                             : "r"(addr));
            }
            #pragma unroll
            for (int mt = 0; mt < 4; mt++)
                #pragma unroll
                for (int nt = 0; nt < 8; nt++) {
                    asm volatile(
                        "mma.sync.aligned.m16n8k16.row.col.f32.f16.f16.f32 "
                        "{%0,%1,%2,%3}, {%4,%5,%6,%7}, {%8,%9}, {%0,%1,%2,%3};\n"
                        : "+f"(acc[mt][nt][0]), "+f"(acc[mt][nt][1]),
                          "+f"(acc[mt][nt][2]), "+f"(acc[mt][nt][3])
                        : "r"(a[mt][0]), "r"(a[mt][1]), "r"(a[mt][2]), "r"(a[mt][3]),
                          "r"(bf[nt][0]), "r"(bf[nt][1]));
                }
        }
        __syncthreads();
        if (i + 2 < NCHUNK) load_chunk(i + 2, st);
    }

    #pragma unroll
    for (int mt = 0; mt < 4; mt++) {
        int mrow = m0 + wm + mt*16;
        #pragma unroll
        for (int nt = 0; nt < 8; nt++) {
            int n = n0 + wn + nt*8 + 2*tig;
            float bx = bp1[n], by = bp1[n+1];
            {
                size_t r = (size_t)(mrow + gid);
                float2 xv = *(const float2*)&x[r*BDIM + n];
                float2 o;
                o.x = acc[mt][nt][0] + xv.x + bx;
                o.y = acc[mt][nt][1] + xv.y + by;
                *(float2*)&g_x2[r*BDIM + n] = o;
            }
            {
                size_t r = (size_t)(mrow + gid + 8);
                float2 xv = *(const float2*)&x[r*BDIM + n];
                float2 o;
                o.x = acc[mt][nt][2] + xv.x + bx;
                o.y = acc[mt][nt][3] + xv.y + by;
                *(float2*)&g_x2[r*BDIM + n] = o;
            }
        }
    }
}

// ------ spool: LN-folded scores + sigmoid + attn + sums + tensor-core pooling ------
#define RPB 32
#define XHS 520                              // fp16 tile row stride (halves)
#define SM_SPOOL (RPB*BDIM*4 + RPB*XHS*2)    // 65536 + 33280 = 98816
__global__ __launch_bounds__(256, 2) void k_spool(float* __restrict__ attn_out) {
    extern __shared__ char smem_raw[];
    float*  sx  = (float*)smem_raw;                       // [RPB][512] fp32
    __half* sxh = (__half*)(smem_raw + RPB*BDIM*4);       // [RPB][XHS] fp16
    __shared__ __half swh[32][40];                        // a*rstd fp16, [c][s]
    __shared__ float stats[RPB][2];
    int b = blockIdx.y, s0 = blockIdx.x * RPB;
    int tid = threadIdx.x, w = tid >> 5, lane = tid & 31;

    // stage x2: fp32 for scores/stats, fp16 for pooling MMA
    {
        const float4* xg = (const float4*)&g_x2[((size_t)b*SLEN + s0)*BDIM];
        float4* sx4 = (float4*)sx;
        #pragma unroll
        for (int i = 0; i < 16; i++) {
            int idx = tid + i*256;
            float4 v = xg[idx];
            sx4[idx] = v;
            int s = idx >> 7, dq = (idx & 127) * 4;
            __half2 h0 = __floats2half2_rn(v.x, v.y);
            __half2 h1 = __floats2half2_rn(v.z, v.w);
            uint32_t u0 = *reinterpret_cast<uint32_t*>(&h0);
            uint32_t u1 = *reinterpret_cast<uint32_t*>(&h1);
            *reinterpret_cast<uint2*>(&sxh[(size_t)s*XHS + dq]) = make_uint2(u0, u1);
        }
    }
    __syncthreads();

    // stats: warp w -> rows 4w..4w+3 (lane-stride-32 slices, conflict-free)
    #pragma unroll
    for (int k = 0; k < 4; k++) {
        int r = w*4 + k;
        float sum = 0.f, sq = 0.f;
        #pragma unroll
        for (int i = 0; i < 16; i++) {
            float v = sx[r*BDIM + lane + 32*i];
            sum += v; sq += v*v;
        }
        #pragma unroll
        for (int off = 16; off; off >>= 1) {
            sum += __shfl_xor_sync(0xffffffffu, sum, off);
            sq  += __shfl_xor_sync(0xffffffffu, sq,  off);
        }
        if (lane == 0) {
            float mean = sum * (1.f/512.f);
            float var  = sq  * (1.f/512.f) - mean*mean;
            stats[r][0] = mean;
            stats[r][1] = rsqrtf(var + 1e-5f);
        }
    }

    // register-resident Wg slice: warp w owns c = 4w..4w+3 (lane-stride-32)
    float Wreg[4][16], Gs[4], Bs[4];
    #pragma unroll
    for (int j = 0; j < 4; j++) {
        int c = w*4 + j;
        #pragma unroll
        for (int i = 0; i < 16; i++)
            Wreg[j][i] = g_WqT[c*BDIM + lane + 32*i];
        Gs[j] = g_Gs[c];
        Bs[j] = g_Bs[c];
    }
    __syncthreads();

    float accA[4] = {0.f,0.f,0.f,0.f}, accM[4] = {0.f,0.f,0.f,0.f};
    for (int r = 0; r < RPB; r++) {
        float xv[16];
        #pragma unroll
        for (int i = 0; i < 16; i++) xv[i] = sx[r*BDIM + lane + 32*i];
        float v0 = 0.f, v1 = 0.f, v2 = 0.f, v3 = 0.f;
        #pragma unroll
        for (int i = 0; i < 16; i++) {
            v0 += xv[i]*Wreg[0][i];
            v1 += xv[i]*Wreg[1][i];
            v2 += xv[i]*Wreg[2][i];
            v3 += xv[i]*Wreg[3][i];
        }
        #pragma unroll
        for (int off = 16; off; off >>= 1) {
            v0 += __shfl_xor_sync(0xffffffffu, v0, off);
            v1 += __shfl_xor_sync(0xffffffffu, v1, off);
            v2 += __shfl_xor_sync(0xffffffffu, v2, off);
            v3 += __shfl_xor_sync(0xffffffffu, v3, off);
        }
        if (lane == 0) {
            float mean = stats[r][0], rstd = stats[r][1];
            float vv0 = rstd*v0 - rstd*mean*Gs[0] + Bs[0];
            float vv1 = rstd*v1 - rstd*mean*Gs[1] + Bs[1];
            float vv2 = rstd*v2 - rstd*mean*Gs[2] + Bs[2];
            float vv3 = rstd*v3 - rstd*mean*Gs[3] + Bs[3];
            float as[4];
            as[0] = 1.f/(1.f + expf(-(vv0 - LOGS)));
            as[1] = 1.f/(1.f + expf(-(vv1 - LOGS)));
            as[2] = 1.f/(1.f + expf(-(vv2 - LOGS)));
            as[3] = 1.f/(1.f + expf(-(vv3 - LOGS)));
            #pragma unroll
            for (int j = 0; j < 4; j++) {
                int c = w*4 + j;
                swh[c][r] = __float2half(as[j] * rstd);
                int h = c & 15, n = c >> 4;
                attn_out[(((size_t)b*16 + h)*2 + n)*SLEN + s0 + r] = as[j];
                accA[j] += as[j];
                accM[j] += as[j] * rstd * mean;
            }
        }
    }
    if (lane == 0) {
        #pragma unroll
        for (int j = 0; j < 4; j++) {
            atomicAdd(&g_A[b*NC + w*4 + j],  accA[j]);
            atomicAdd(&g_Mw[b*NC + w*4 + j], accM[j]);
        }
    }
    __syncthreads();

    // pooling via tensor cores: P[c][d] = sum_s swh[c][s] * sxh[s][d]
    // per warp: m=32 (c), n=64 (d range w*64..+63), k=32 (s)
    {
        int n0 = w * 64;
        uint32_t swb = s2u(&swh[0][0]);
        uint32_t xhb = s2u(sxh);
        int arow = (lane & 7) + ((lane >> 3) & 1) * 8;
        int acol = (lane >> 4) * 8;
        int krow = lane & 15;

        float pacc[2][8][4];
        #pragma unroll
        for (int mt = 0; mt < 2; mt++)
            #pragma unroll
            for (int nt = 0; nt < 8; nt++)
                #pragma unroll
                for (int q = 0; q < 4; q++) pacc[mt][nt][q] = 0.f;

        #pragma unroll
        for (int kt = 0; kt < 2; kt++) {
            uint32_t afr[2][4];
            #pragma unroll
            for (int mt = 0; mt < 2; mt++) {
                uint32_t addr = swb + (uint32_t)((mt*16 + arow)*40 + kt*16 + acol) * 2u;
                asm volatile("ldmatrix.sync.aligned.m8n8.x4.shared.b16 {%0,%1,%2,%3}, [%4];"
                             : "=r"(afr[mt][0]), "=r"(afr[mt][1]), "=r"(afr[mt][2]), "=r"(afr[mt][3])
                             : "r"(addr));
            }
            uint32_t bfr[8][2];
            #pragma unroll
            for (int nt = 0; nt < 8; nt++) {
                uint32_t addr = xhb + (uint32_t)((kt*16 + krow)*XHS + n0 + nt*8) * 2u;
                asm volatile("ldmatrix.sync.aligned.m8n8.x2.trans.shared.b16 {%0,%1}, [%2];"
                             : "=r"(bfr[nt][0]), "=r"(bfr[nt][1])
                             : "r"(addr));
            }
            #pragma unroll
            for (int mt = 0; mt < 2; mt++)
                #pragma unroll
                for (int nt = 0; nt < 8; nt++) {
                    asm volatile(
                        "mma.sync.aligned.m16n8k16.row.col.f32.f16.f16.f32 "
                        "{%0,%1,%2,%3}, {%4,%5,%6,%7}, {%8,%9}, {%0,%1,%2,%3};\n"
                        : "+f"(pacc[mt][nt][0]), "+f"(pacc[mt][nt][1]),
                          "+f"(pacc[mt][nt][2]), "+f"(pacc[mt][nt][3])
                        : "r"(afr[mt][0]), "r"(afr[mt][1]), "r"(afr[mt][2]), "r"(afr[mt][3]),
                          "r"(bfr[nt][0]), "r"(bfr[nt][1]));
                }
        }

        int gid = lane >> 2, tig = lane & 3;
        size_t pbase = (((size_t)b*64 + blockIdx.x)*NC)*BDIM;
        #pragma unroll
        for (int mt = 0; mt < 2; mt++) {
            #pragma unroll
            for (int nt = 0; nt < 8; nt++) {
                int c0 = mt*16 + gid;
                int dcol = n0 + nt*8 + 2*tig;
                float2 lo = make_float2(pacc[mt][nt][0], pacc[mt][nt][1]);
                float2 hi = make_float2(pacc[mt][nt][2], pacc[mt][nt][3]);
                *(float2*)&g_Ppart[pbase + (size_t)c0*BDIM + dcol]       = lo;
                *(float2*)&g_Ppart[pbase + (size_t)(c0+8)*BDIM + dcol]   = hi;
            }
        }
    }
}

// ---------------- combine partials -> pooled_xn ----------------
__global__ void k_pooled(const float* __restrict__ ln_g, const float* __restrict__ ln_b) {
    int c = blockIdx.x, b = blockIdx.y, d = threadIdx.x;
    float p = 0.f;
    #pragma unroll 16
    for (int sc = 0; sc < 64; sc++)
        p += g_Ppart[(((size_t)b*64 + sc)*NC + c)*BDIM + d];
    float val = ln_g[d]*(p - g_Mw[b*NC + c]) + ln_b[d]*g_A[b*NC + c];
    g_pooled[((size_t)b*NC + c)*BDIM + d] = val;
}

// ---------------- fused tail: ohead -> oproj -> head ----------------
__global__ __launch_bounds__(512) void k_tail(const float* __restrict__ Wkv,
                                              const float* __restrict__ Wproj,
                                              const float* __restrict__ bproj,
                                              const float* __restrict__ g2,
                                              const float* __restrict__ b2,
                                              const float* __restrict__ Wc1,
                                              const float* __restrict__ bc1,
                                              const float* __restrict__ Wc2,
                                              const float* __restrict__ bc2,
                                              float* __restrict__ out) {
    __shared__ float s1[BDIM];
    __shared__ float s2[BDIM];
    int b = blockIdx.x, n = blockIdx.y;
    int j = threadIdx.x;

    {
        int h = j >> 5;
        const float* pp = &g_pooled[((size_t)b*NC + n*16 + h)*BDIM];
        float acc = 0.f;
        #pragma unroll 16
        for (int d = 0; d < BDIM; d++)
            acc += pp[d] * Wkv[(size_t)d*1024 + 512 + j];
        s1[j] = acc;
    }
    __syncthreads();

    {
        float acc = 0.f;
        #pragma unroll 16
        for (int d = 0; d < BDIM; d++)
            acc += s1[d] * Wproj[(size_t)d*BDIM + j];
        s2[j] = acc + bproj[j];
    }
    __syncthreads();

    float v = s2[j];
    s1[j] = v; __syncthreads();
    for (int off = 256; off; off >>= 1) {
        if (j < off) s1[j] += s1[j + off];
        __syncthreads();
    }
    float mean = s1[0] * (1.f/512.f);
    __syncthreads();
    float dv = v - mean;
    s1[j] = dv*dv; __syncthreads();
    for (int off = 256; off; off >>= 1) {
        if (j < off) s1[j] += s1[j + off];
        __syncthreads();
    }
    float rstd = rsqrtf(s1[0]*(1.f/512.f) + 1e-5f);
    __syncthreads();
    s2[j] = dv*rstd*g2[j] + b2[j];
    __syncthreads();
    float hj = bc1[j];
    #pragma unroll 16
    for (int d = 0; d < BDIM; d++)
        hj += s2[d] * Wc1[(size_t)d*BDIM + j];
    hj = fmaxf(hj, 0.f);
    s1[j] = hj * Wc2[j];
    __syncthreads();
    for (int off = 256; off; off >>= 1) {
        if (j < off) s1[j] += s1[j + off];
        __syncthreads();
    }
    if (j == 0) out[b*2 + n] = s1[0] + bc2[0];
}

// ---------------- launch ----------------
extern "C" void kernel_launch(void* const* d_in, const int* in_sizes, int n_in,
                              void* d_out, int out_size) {
    const float* x      = (const float*)d_in[0];
    const float* wave1  = (const float*)d_in[1];
    const float* wave2  = (const float*)d_in[2];
    const float* wave3  = (const float*)d_in[3];
    const float* Wp1    = (const float*)d_in[4];
    const float* bp1    = (const float*)d_in[5];
    const float* cls    = (const float*)d_in[6];
    const float* ln1_g  = (const float*)d_in[7];
    const float* ln1_b  = (const float*)d_in[8];
    const float* Wq     = (const float*)d_in[9];
    const float* Wkv    = (const float*)d_in[10];
    const float* Wproj  = (const float*)d_in[11];
    const float* bproj  = (const float*)d_in[12];
    const float* ln2_g  = (const float*)d_in[13];
    const float* ln2_b  = (const float*)d_in[14];
    const float* Wc1    = (const float*)d_in[15];
    const float* bc1    = (const float*)d_in[16];
    const float* Wc2    = (const float*)d_in[17];
    const float* bc2    = (const float*)d_in[18];

    float* out  = (float*)d_out;
    float* attn = out + BATCH*2;   // logits [32,2] first, then attn [32,16,2,2048]

    static int smem_set = 0;
    if (!smem_set) {
        cudaFuncSetAttribute(k_conv,  cudaFuncAttributeMaxDynamicSharedMemorySize, SM_CONV);
        cudaFuncSetAttribute(k_gemm,  cudaFuncAttributeMaxDynamicSharedMemorySize, SM_GEMM);
        cudaFuncSetAttribute(k_spool, cudaFuncAttributeMaxDynamicSharedMemorySize, SM_SPOOL);
        smem_set = 1;
    }

    {
        dim3 g(BDIM/CDC, SLEN/CTS, BATCH);
        k_conv<<<g, 512, SM_CONV>>>(x, wave1, wave2, wave3);       // 1
    }
    k_prep<<<48, 512>>>(cls, Wq, Wkv, Wp1, ln1_g, ln1_b);          // 2
    {
        dim3 g(BDIM/GN, NROWS/GM);
        k_gemm<<<g, 256, SM_GEMM>>>(x, bp1);                       // 3
    }
    {
        dim3 g(SLEN/RPB, BATCH);                                   // (64, 32)
        k_spool<<<g, 256, SM_SPOOL>>>(attn);                       // 4  <- profiled
    }
    {
        dim3 g(NC, BATCH);
        k_pooled<<<g, BDIM>>>(ln1_g, ln1_b);                       // 5
    }
    {
        dim3 g(BATCH, 2);
        k_tail<<<g, BDIM>>>(Wkv, Wproj, bproj, ln2_g, ln2_b,
                            Wc1, bc1, Wc2, bc2, out);              // 6
    }
}

// round 17
// speedup vs baseline: 1.1724x; 1.1241x over previous
#include <cuda_runtime.h>
#include <cuda_fp16.h>
#include <math.h>
#include <stdint.h>

#define BDIM 512
#define SLEN 2048
#define BATCH 32
#define NROWS (BATCH*SLEN)
#define KS 19
#define NC 32                    // NCLS * H
#define LOGS 7.6246189861594f    // log(2048)

// ---------------- scratch (static device globals; no allocs) ----------------
__device__ float  g_WqT[NC*BDIM];                  // Wg = ln_g ⊙ WqEff, [c][d]
__device__ float  g_Gs[NC];                        // sum_d Wg[c][d]
__device__ float  g_Bs[NC];                        // sum_d ln_b[d]*W[c][d]
__device__ __half g_Wp1h[BDIM*BDIM];               // Wp1 transposed [n][k], fp16
__device__ __half g_posh[(size_t)NROWS*BDIM];      // conv output, fp16
__device__ float  g_x2[(size_t)NROWS*BDIM];        // x + pos@Wp1 + bp1
__device__ float  g_Ppart[(size_t)BATCH*64*NC*BDIM]; // pooling partials [b][chunk][c][d]
__device__ float  g_A[BATCH*NC];                   // sum attn
__device__ float  g_Mw[BATCH*NC];                  // sum attn*rstd*mean
__device__ float  g_pooled[BATCH*NC*BDIM];         // pooled xn [b][c][d]

// ---------------- helpers ----------------
__device__ __forceinline__ uint32_t s2u(const void* p) {
    uint32_t a;
    asm("{ .reg .u64 t; cvta.to.shared.u64 t, %1; cvt.u32.u64 %0, t; }" : "=r"(a) : "l"(p));
    return a;
}

// ---------------- conv (wavelet coefs fused, smem-tiled) ----------------
#define CTS 64
#define CDC 128
#define SM_CONV ((CTS+18)*CDC*4 + KS*CDC*4)     // 51712
__global__ __launch_bounds__(512) void k_conv(const float* __restrict__ x,
                                              const float* __restrict__ w1,
                                              const float* __restrict__ w2,
                                              const float* __restrict__ w3) {
    extern __shared__ char smc[];
    float (*tile)[CDC]  = (float(*)[CDC])smc;
    float (*scoef)[CDC] = (float(*)[CDC])(smc + (CTS+18)*CDC*4);
    int b  = blockIdx.z;
    int s0 = blockIdx.y * CTS;
    int d0 = blockIdx.x * CDC;
    int tid = threadIdx.x;

    const float C = 0.8673250705840776f;
    const float* ws[3] = {w1, w2, w3};
    for (int i = tid; i < KS*CDC; i += 512) {
        int t = i >> 7, d = i & (CDC-1);
        int dg = d0 + d;
        float xs = (float)(t - 9);
        float sum = 0.f;
        #pragma unroll
        for (int wv = 0; wv < 3; wv++) {
            float scale = ws[wv][dg];
            float shift = ws[wv][BDIM + dg];
            float u = (xs - shift) / scale;
            sum += C * (1.f - u*u) * expf(-0.5f*u*u) * rsqrtf(fabsf(scale));
        }
        scoef[t][d] = sum;
    }

    const int NV = (CTS + 18) * (CDC / 4);
    for (int i = tid; i < NV; i += 512) {
        int r = i / (CDC/4), c4 = i % (CDC/4);
        int s = s0 - 9 + r;
        float4 v = make_float4(0.f, 0.f, 0.f, 0.f);
        if (s >= 0 && s < SLEN)
            v = *(const float4*)&x[((size_t)b*SLEN + s)*BDIM + d0 + c4*4];
        *(float4*)&tile[r][c4*4] = v;
    }
    __syncthreads();

    int dL = tid & (CDC - 1);
    int g  = tid >> 7;
    float coef[KS];
    #pragma unroll
    for (int t = 0; t < KS; t++) coef[t] = scoef[t][dL];

    float acc[16];
    #pragma unroll
    for (int i = 0; i < 16; i++) acc[i] = 0.f;

    #pragma unroll
    for (int j = 0; j < 34; j++) {
        float v = tile[g*16 + j][dL];
        #pragma unroll
        for (int t = 0; t < KS; t++) {
            int s = j - t;
            if (s >= 0 && s < 16) acc[s] += v * coef[t];
        }
    }
    size_t base = ((size_t)b*SLEN + s0 + g*16)*BDIM + d0 + dL;
    #pragma unroll
    for (int i = 0; i < 16; i++)
        g_posh[base + (size_t)i*BDIM] = __float2half(acc[i]);
}

// ------- prep: Wg/Gs/Bs (blocks 0..31); Wp1 fp16 transpose (32..47) -------
__global__ __launch_bounds__(512) void k_prep(const float* __restrict__ cls,
                                              const float* __restrict__ Wq,
                                              const float* __restrict__ Wkv,
                                              const float* __restrict__ Wp1,
                                              const float* __restrict__ ln_g,
                                              const float* __restrict__ ln_b) {
    if (blockIdx.x < 32) {
        __shared__ float q[2][BDIM];
        __shared__ float red2[BDIM];
        int j = threadIdx.x;
        #pragma unroll
        for (int n = 0; n < 2; n++) {
            float acc = 0.f;
            #pragma unroll 16
            for (int d = 0; d < BDIM; d++)
                acc += __ldg(&cls[n*BDIM + d]) * Wq[(size_t)d*BDIM + j];
            q[n][j] = acc;
        }
        __syncthreads();
        int c = blockIdx.x, d = threadIdx.x;
        int n = c >> 4, h = c & 15;
        float acc = 0.f;
        #pragma unroll
        for (int hd = 0; hd < 32; hd++)
            acc += Wkv[(size_t)d*1024 + h*32 + hd] * q[n][h*32 + hd];
        acc *= 0.17677669529663689f;
        float wg = acc * ln_g[d];
        g_WqT[c*BDIM + d] = wg;
        red2[d] = wg;
        __syncthreads();
        for (int off = 256; off; off >>= 1) {
            if (d < off) red2[d] += red2[d + off];
            __syncthreads();
        }
        if (d == 0) g_Gs[c] = red2[0];
        __syncthreads();
        red2[d] = acc * ln_b[d];
        __syncthreads();
        for (int off = 256; off; off >>= 1) {
            if (d < off) red2[d] += red2[d + off];
            __syncthreads();
        }
        if (d == 0) g_Bs[c] = red2[0];
        if (d < BATCH) { g_A[d*NC + c] = 0.f; g_Mw[d*NC + c] = 0.f; }
    } else {
        int nb = (blockIdx.x - 32) * 32;
        int k = threadIdx.x;
        #pragma unroll
        for (int i = 0; i < 32; i++)
            g_Wp1h[(size_t)(nb + i)*BDIM + k] = __float2half(Wp1[(size_t)k*BDIM + nb + i]);
    }
}

// -------- x2 = x + pos @ Wp1 + bp1 (fp16 mma.sync + ldmatrix, 2-stage, 2 CTA/SM) --------
#define GM 128
#define GN 128
#define KCH 64
#define NCHUNK 8
#define AST 72
#define STG_H ((GM + GN) * AST)          // 18432 halves
#define SM_GEMM (2*STG_H*2)              // 73728 bytes

__global__ __launch_bounds__(256, 2) void k_gemm(const float* __restrict__ x,
                                                 const float* __restrict__ bp1) {
    extern __shared__ __half smh[];
    uint32_t sb = s2u(smh);
    int tid  = threadIdx.x;
    int m0   = blockIdx.y * GM;
    int n0   = blockIdx.x * GN;
    int warp = tid >> 5, lane = tid & 31;
    int wm   = (warp & 1) * 64;          // 2 warps along m
    int wn   = (warp >> 1) * 32;         // 4 warps along n (32 each)
    int gid  = lane >> 2, tig = lane & 3;

    float acc[4][4][4];
    #pragma unroll
    for (int i = 0; i < 4; i++)
        #pragma unroll
        for (int j = 0; j < 4; j++)
            #pragma unroll
            for (int r = 0; r < 4; r++) acc[i][j][r] = 0.f;

    auto load_chunk = [&](int ch, int st) {
        uint32_t ab = sb + (uint32_t)(st * STG_H) * 2u;
        uint32_t bb = ab + GM*AST*2u;
        const __half* As = g_posh + (size_t)m0 * BDIM + ch * KCH;
        #pragma unroll
        for (int it = 0; it < 4; it++) {            // A: 128 rows x 8 x 16B
            int idx = tid + it * 256;
            int r = idx >> 3, c = idx & 7;
            uint32_t dst = ab + (uint32_t)(r*144 + c*16);
            const __half* src = As + (size_t)r * BDIM + c * 8;
            asm volatile("cp.async.cg.shared.global [%0], [%1], 16;" :: "r"(dst), "l"(src));
        }
        const __half* Bs = g_Wp1h + (size_t)n0 * BDIM + ch * KCH;
        #pragma unroll
        for (int it = 0; it < 4; it++) {            // B: 128 rows x 8 x 16B
            int idx = tid + it * 256;
            int r = idx >> 3, c = idx & 7;
            uint32_t dst = bb + (uint32_t)(r*144 + c*16);
            const __half* src = Bs + (size_t)r * BDIM + c * 8;
            asm volatile("cp.async.cg.shared.global [%0], [%1], 16;" :: "r"(dst), "l"(src));
        }
        asm volatile("cp.async.commit_group;" ::: "memory");
    };

    load_chunk(0, 0);
    load_chunk(1, 1);

    for (int i = 0; i < NCHUNK; i++) {
        int st = i & 1;
        if (i >= NCHUNK - 1) asm volatile("cp.async.wait_group 0;" ::: "memory");
        else                 asm volatile("cp.async.wait_group 1;" ::: "memory");
        __syncthreads();

        uint32_t abase = sb + (uint32_t)(st * STG_H) * 2u;
        uint32_t bbase = abase + GM*AST*2u;
        int arow_off = (lane & 7) + ((lane >> 3) & 1) * 8;
        int acol_off = (lane >> 4) * 8;
        int brow_off = (lane & 7);
        int bcol_off = ((lane >> 3) & 1) * 8;

        #pragma unroll
        for (int ks = 0; ks < 4; ks++) {
            uint32_t a[4][4], bf[4][2];
            #pragma unroll
            for (int mt = 0; mt < 4; mt++) {
                int m = wm + mt*16 + arow_off;
                uint32_t addr = abase + (uint32_t)(m*144 + (ks*16 + acol_off)*2);
                asm volatile("ldmatrix.sync.aligned.m8n8.x4.shared.b16 {%0,%1,%2,%3}, [%4];"
                             : "=r"(a[mt][0]), "=r"(a[mt][1]), "=r"(a[mt][2]), "=r"(a[mt][3])
                             : "r"(addr));
            }
            #pragma unroll
            for (int nt = 0; nt < 4; nt++) {
                int n = wn + nt*8 + brow_off;
                uint32_t addr = bbase + (uint32_t)(n*144 + (ks*16 + bcol_off)*2);
                asm volatile("ldmatrix.sync.aligned.m8n8.x2.shared.b16 {%0,%1}, [%2];"
                             : "=r"(bf[nt][0]), "=r"(bf[nt][1])
                             : "r"(addr));
            }
            #pragma unroll
            for (int mt = 0; mt < 4; mt++)
                #pragma unroll
                for (int nt = 0; nt < 4; nt++) {
                    asm volatile(
                        "mma.sync.aligned.m16n8k16.row.col.f32.f16.f16.f32 "
                        "{%0,%1,%2,%3}, {%4,%5,%6,%7}, {%8,%9}, {%0,%1,%2,%3};\n"
                        : "+f"(acc[mt][nt][0]), "+f"(acc[mt][nt][1]),
                          "+f"(acc[mt][nt][2]), "+f"(acc[mt][nt][3])
                        : "r"(a[mt][0]), "r"(a[mt][1]), "r"(a[mt][2]), "r"(a[mt][3]),
                          "r"(bf[nt][0]), "r"(bf[nt][1]));
                }
        }
        __syncthreads();
        if (i + 2 < NCHUNK) load_chunk(i + 2, st);
    }

    #pragma unroll
    for (int mt = 0; mt < 4; mt++) {
        int mrow = m0 + wm + mt*16;
        #pragma unroll
        for (int nt = 0; nt < 4; nt++) {
            int n = n0 + wn + nt*8 + 2*tig;
            float bx = bp1[n], by = bp1[n+1];
            {
                size_t r = (size_t)(mrow + gid);
                float2 xv = *(const float2*)&x[r*BDIM + n];
                float2 o;
                o.x = acc[mt][nt][0] + xv.x + bx;
                o.y = acc[mt][nt][1] + xv.y + by;
                *(float2*)&g_x2[r*BDIM + n] = o;
            }
            {
                size_t r = (size_t)(mrow + gid + 8);
                float2 xv = *(const float2*)&x[r*BDIM + n];
                float2 o;
                o.x = acc[mt][nt][2] + xv.x + bx;
                o.y = acc[mt][nt][3] + xv.y + by;
                *(float2*)&g_x2[r*BDIM + n] = o;
            }
        }
    }
}

// ------ spool: LN-folded scores + sigmoid + attn + sums + tensor-core pooling ------
#define RPB 32
#define XHS 520                              // fp16 tile row stride (halves)
#define SM_SPOOL (RPB*BDIM*4 + RPB*XHS*2)    // 65536 + 33280 = 98816
__global__ __launch_bounds__(256, 2) void k_spool(float* __restrict__ attn_out) {
    extern __shared__ char smem_raw[];
    float*  sx  = (float*)smem_raw;                       // [RPB][512] fp32
    __half* sxh = (__half*)(smem_raw + RPB*BDIM*4);       // [RPB][XHS] fp16
    __shared__ __half swh[32][40];                        // a*rstd fp16, [c][s]
    __shared__ float stats[RPB][2];
    int b = blockIdx.y, s0 = blockIdx.x * RPB;
    int tid = threadIdx.x, w = tid >> 5, lane = tid & 31;

    // stage x2: fp32 for scores/stats, fp16 for pooling MMA
    {
        const float4* xg = (const float4*)&g_x2[((size_t)b*SLEN + s0)*BDIM];
        float4* sx4 = (float4*)sx;
        #pragma unroll
        for (int i = 0; i < 16; i++) {
            int idx = tid + i*256;
            float4 v = xg[idx];
            sx4[idx] = v;
            int s = idx >> 7, dq = (idx & 127) * 4;
            __half2 h0 = __floats2half2_rn(v.x, v.y);
            __half2 h1 = __floats2half2_rn(v.z, v.w);
            uint32_t u0 = *reinterpret_cast<uint32_t*>(&h0);
            uint32_t u1 = *reinterpret_cast<uint32_t*>(&h1);
            *reinterpret_cast<uint2*>(&sxh[(size_t)s*XHS + dq]) = make_uint2(u0, u1);
        }
    }
    __syncthreads();

    // stats: warp w -> rows 4w..4w+3 (lane-stride-32 slices, conflict-free)
    #pragma unroll
    for (int k = 0; k < 4; k++) {
        int r = w*4 + k;
        float sum = 0.f, sq = 0.f;
        #pragma unroll
        for (int i = 0; i < 16; i++) {
            float v = sx[r*BDIM + lane + 32*i];
            sum += v; sq += v*v;
        }
        #pragma unroll
        for (int off = 16; off; off >>= 1) {
            sum += __shfl_xor_sync(0xffffffffu, sum, off);
            sq  += __shfl_xor_sync(0xffffffffu, sq,  off);
        }
        if (lane == 0) {
            float mean = sum * (1.f/512.f);
            float var  = sq  * (1.f/512.f) - mean*mean;
            stats[r][0] = mean;
            stats[r][1] = rsqrtf(var + 1e-5f);
        }
    }

    // register-resident Wg slice: warp w owns c = 4w..4w+3 (lane-stride-32)
    float Wreg[4][16];
    #pragma unroll
    for (int j = 0; j < 4; j++) {
        int c = w*4 + j;
        #pragma unroll
        for (int i = 0; i < 16; i++)
            Wreg[j][i] = g_WqT[c*BDIM + lane + 32*i];
    }
    // per-lane Gs/Bs for c = w*4 + (lane&3) -- avoids dynamic reg indexing
    int lj = lane & 3;
    float Gsl = g_Gs[w*4 + lj];
    float Bsl = g_Bs[w*4 + lj];
    __syncthreads();

    float accA = 0.f, accM = 0.f;
    for (int r = 0; r < RPB; r++) {
        float xv[16];
        #pragma unroll
        for (int i = 0; i < 16; i++) xv[i] = sx[r*BDIM + lane + 32*i];
        float v0 = 0.f, v1 = 0.f, v2 = 0.f, v3 = 0.f;
        #pragma unroll
        for (int i = 0; i < 16; i++) {
            v0 += xv[i]*Wreg[0][i];
            v1 += xv[i]*Wreg[1][i];
            v2 += xv[i]*Wreg[2][i];
            v3 += xv[i]*Wreg[3][i];
        }
        #pragma unroll
        for (int off = 16; off; off >>= 1) {
            v0 += __shfl_xor_sync(0xffffffffu, v0, off);
            v1 += __shfl_xor_sync(0xffffffffu, v1, off);
            v2 += __shfl_xor_sync(0xffffffffu, v2, off);
            v3 += __shfl_xor_sync(0xffffffffu, v3, off);
        }
        // all lanes hold full sums; lane j in {0..3} handles c = w*4 + j
        float mean = stats[r][0], rstd = stats[r][1];
        float vj = v0;
        vj = (lj == 1) ? v1 : vj;
        vj = (lj == 2) ? v2 : vj;
        vj = (lj == 3) ? v3 : vj;
        float vv = rstd*vj - rstd*mean*Gsl + Bsl;
        float a = 1.f/(1.f + expf(-(vv - LOGS)));
        if (lane < 4) {
            int c = w*4 + lj;
            swh[c][r] = __float2half(a * rstd);
            int h = c & 15, n = c >> 4;
            attn_out[(((size_t)b*16 + h)*2 + n)*SLEN + s0 + r] = a;
            accA += a;
            accM += a * rstd * mean;
        }
    }
    if (lane < 4) {
        atomicAdd(&g_A[b*NC + w*4 + lj],  accA);
        atomicAdd(&g_Mw[b*NC + w*4 + lj], accM);
    }
    __syncthreads();

    // pooling via tensor cores: P[c][d] = sum_s swh[c][s] * sxh[s][d]
    // per warp: m=32 (c), n=64 (d range w*64..+63), k=32 (s)
    {
        int n0 = w * 64;
        uint32_t swb = s2u(&swh[0][0]);
        uint32_t xhb = s2u(sxh);
        int arow = (lane & 7) + ((lane >> 3) & 1) * 8;
        int acol = (lane >> 4) * 8;
        int krow = lane & 15;

        float pacc[2][8][4];
        #pragma unroll
        for (int mt = 0; mt < 2; mt++)
            #pragma unroll
            for (int nt = 0; nt < 8; nt++)
                #pragma unroll
                for (int q = 0; q < 4; q++) pacc[mt][nt][q] = 0.f;

        #pragma unroll
        for (int kt = 0; kt < 2; kt++) {
            uint32_t afr[2][4];
            #pragma unroll
            for (int mt = 0; mt < 2; mt++) {
                uint32_t addr = swb + (uint32_t)((mt*16 + arow)*40 + kt*16 + acol) * 2u;
                asm volatile("ldmatrix.sync.aligned.m8n8.x4.shared.b16 {%0,%1,%2,%3}, [%4];"
                             : "=r"(afr[mt][0]), "=r"(afr[mt][1]), "=r"(afr[mt][2]), "=r"(afr[mt][3])
                             : "r"(addr));
            }
            uint32_t bfr[8][2];
            #pragma unroll
            for (int nt = 0; nt < 8; nt++) {
                uint32_t addr = xhb + (uint32_t)((kt*16 + krow)*XHS + n0 + nt*8) * 2u;
                asm volatile("ldmatrix.sync.aligned.m8n8.x2.trans.shared.b16 {%0,%1}, [%2];"
                             : "=r"(bfr[nt][0]), "=r"(bfr[nt][1])
                             : "r"(addr));
            }
            #pragma unroll
            for (int mt = 0; mt < 2; mt++)
                #pragma unroll
                for (int nt = 0; nt < 8; nt++) {
                    asm volatile(
                        "mma.sync.aligned.m16n8k16.row.col.f32.f16.f16.f32 "
                        "{%0,%1,%2,%3}, {%4,%5,%6,%7}, {%8,%9}, {%0,%1,%2,%3};\n"
                        : "+f"(pacc[mt][nt][0]), "+f"(pacc[mt][nt][1]),
                          "+f"(pacc[mt][nt][2]), "+f"(pacc[mt][nt][3])
                        : "r"(afr[mt][0]), "r"(afr[mt][1]), "r"(afr[mt][2]), "r"(afr[mt][3]),
                          "r"(bfr[nt][0]), "r"(bfr[nt][1]));
                }
        }

        int gid = lane >> 2, tig = lane & 3;
        size_t pbase = (((size_t)b*64 + blockIdx.x)*NC)*BDIM;
        #pragma unroll
        for (int mt = 0; mt < 2; mt++) {
            #pragma unroll
            for (int nt = 0; nt < 8; nt++) {
                int c0 = mt*16 + gid;
                int dcol = n0 + nt*8 + 2*tig;
                float2 lo = make_float2(pacc[mt][nt][0], pacc[mt][nt][1]);
                float2 hi = make_float2(pacc[mt][nt][2], pacc[mt][nt][3]);
                *(float2*)&g_Ppart[pbase + (size_t)c0*BDIM + dcol]       = lo;
                *(float2*)&g_Ppart[pbase + (size_t)(c0+8)*BDIM + dcol]   = hi;
            }
        }
    }
}

// ---------------- combine partials -> pooled_xn ----------------
__global__ void k_pooled(const float* __restrict__ ln_g, const float* __restrict__ ln_b) {
    int c = blockIdx.x, b = blockIdx.y, d = threadIdx.x;
    float p = 0.f;
    #pragma unroll 16
    for (int sc = 0; sc < 64; sc++)
        p += g_Ppart[(((size_t)b*64 + sc)*NC + c)*BDIM + d];
    float val = ln_g[d]*(p - g_Mw[b*NC + c]) + ln_b[d]*g_A[b*NC + c];
    g_pooled[((size_t)b*NC + c)*BDIM + d] = val;
}

// ---------------- fused tail: ohead -> oproj -> head ----------------
__global__ __launch_bounds__(512) void k_tail(const float* __restrict__ Wkv,
                                              const float* __restrict__ Wproj,
                                              const float* __restrict__ bproj,
                                              const float* __restrict__ g2,
                                              const float* __restrict__ b2,
                                              const float* __restrict__ Wc1,
                                              const float* __restrict__ bc1,
                                              const float* __restrict__ Wc2,
                                              const float* __restrict__ bc2,
                                              float* __restrict__ out) {
    __shared__ float s1[BDIM];
    __shared__ float s2[BDIM];
    int b = blockIdx.x, n = blockIdx.y;
    int j = threadIdx.x;

    {
        int h = j >> 5;
        const float* pp = &g_pooled[((size_t)b*NC + n*16 + h)*BDIM];
        float acc = 0.f;
        #pragma unroll 16
        for (int d = 0; d < BDIM; d++)
            acc += pp[d] * Wkv[(size_t)d*1024 + 512 + j];
        s1[j] = acc;
    }
    __syncthreads();

    {
        float acc = 0.f;
        #pragma unroll 16
        for (int d = 0; d < BDIM; d++)
            acc += s1[d] * Wproj[(size_t)d*BDIM + j];
        s2[j] = acc + bproj[j];
    }
    __syncthreads();

    float v = s2[j];
    s1[j] = v; __syncthreads();
    for (int off = 256; off; off >>= 1) {
        if (j < off) s1[j] += s1[j + off];
        __syncthreads();
    }
    float mean = s1[0] * (1.f/512.f);
    __syncthreads();
    float dv = v - mean;
    s1[j] = dv*dv; __syncthreads();
    for (int off = 256; off; off >>= 1) {
        if (j < off) s1[j] += s1[j + off];
        __syncthreads();
    }
    float rstd = rsqrtf(s1[0]*(1.f/512.f) + 1e-5f);
    __syncthreads();
    s2[j] = dv*rstd*g2[j] + b2[j];
    __syncthreads();
    float hj = bc1[j];
    #pragma unroll 16
    for (int d = 0; d < BDIM; d++)
        hj += s2[d] * Wc1[(size_t)d*BDIM + j];
    hj = fmaxf(hj, 0.f);
    s1[j] = hj * Wc2[j];
    __syncthreads();
    for (int off = 256; off; off >>= 1) {
        if (j < off) s1[j] += s1[j + off];
        __syncthreads();
    }
    if (j == 0) out[b*2 + n] = s1[0] + bc2[0];
}

// ---------------- launch ----------------
extern "C" void kernel_launch(void* const* d_in, const int* in_sizes, int n_in,
                              void* d_out, int out_size) {
    const float* x      = (const float*)d_in[0];
    const float* wave1  = (const float*)d_in[1];
    const float* wave2  = (const float*)d_in[2];
    const float* wave3  = (const float*)d_in[3];
    const float* Wp1    = (const float*)d_in[4];
    const float* bp1    = (const float*)d_in[5];
    const float* cls    = (const float*)d_in[6];
    const float* ln1_g  = (const float*)d_in[7];
    const float* ln1_b  = (const float*)d_in[8];
    const float* Wq     = (const float*)d_in[9];
    const float* Wkv    = (const float*)d_in[10];
    const float* Wproj  = (const float*)d_in[11];
    const float* bproj  = (const float*)d_in[12];
    const float* ln2_g  = (const float*)d_in[13];
    const float* ln2_b  = (const float*)d_in[14];
    const float* Wc1    = (const float*)d_in[15];
    const float* bc1    = (const float*)d_in[16];
    const float* Wc2    = (const float*)d_in[17];
    const float* bc2    = (const float*)d_in[18];

    float* out  = (float*)d_out;
    float* attn = out + BATCH*2;   // logits [32,2] first, then attn [32,16,2,2048]

    static int smem_set = 0;
    if (!smem_set) {
        cudaFuncSetAttribute(k_conv,  cudaFuncAttributeMaxDynamicSharedMemorySize, SM_CONV);
        cudaFuncSetAttribute(k_gemm,  cudaFuncAttributeMaxDynamicSharedMemorySize, SM_GEMM);
        cudaFuncSetAttribute(k_spool, cudaFuncAttributeMaxDynamicSharedMemorySize, SM_SPOOL);
        smem_set = 1;
    }

    {
        dim3 g(BDIM/CDC, SLEN/CTS, BATCH);
        k_conv<<<g, 512, SM_CONV>>>(x, wave1, wave2, wave3);       // 1
    }
    k_prep<<<48, 512>>>(cls, Wq, Wkv, Wp1, ln1_g, ln1_b);          // 2
    {
        dim3 g(BDIM/GN, NROWS/GM);                                 // (4, 512)
        k_gemm<<<g, 256, SM_GEMM>>>(x, bp1);                       // 3
    }
    {
        dim3 g(SLEN/RPB, BATCH);                                   // (64, 32)
        k_spool<<<g, 256, SM_SPOOL>>>(attn);                       // 4  <- profiled
    }
    {
        dim3 g(NC, BATCH);
        k_pooled<<<g, BDIM>>>(ln1_g, ln1_b);                       // 5
    }
    {
        dim3 g(BATCH, 2);
        k_tail<<<g, BDIM>>>(Wkv, Wproj, bproj, ln2_g, ln2_b,
                            Wc1, bc1, Wc2, bc2, out);              // 6
    }
}